// round 6
// baseline (speedup 1.0000x reference)
#include <cuda_runtime.h>
#include <cstdint>
#include <cstddef>

#define NSITES 131072
#define HID    512
#define KTAPS  9
#define EPS    1e-5f

// ---------------------------------------------------------------------------
// Device-global scratch (allocation-free rule)
// ---------------------------------------------------------------------------
__device__ __align__(16) float g_bufA[(size_t)NSITES * HID];
__device__ __align__(16) float g_bufB[(size_t)NSITES * HID];
__device__ __align__(16) float g_featr[(size_t)NSITES * 256];
#define W0_ELEMS ((size_t)2304 * 512)
#define WL_ELEMS ((size_t)4608 * 512)
__device__ __align__(16) float g_W[W0_ELEMS + 7 * WL_ELEMS];

// ---------------------------------------------------------------------------
// Helpers (baseline PTX only — must pass ptxas at .target sm_103)
// ---------------------------------------------------------------------------
__device__ __forceinline__ uint32_t smem_u32(const void* p) {
    uint32_t a;
    asm("{ .reg .u64 t; cvta.to.shared.u64 t, %1; cvt.u32.u64 %0, t; }" : "=r"(a) : "l"(p));
    return a;
}
__device__ __forceinline__ float tf32_rn(float v) {
    uint32_t o;
    asm("cvt.rna.tf32.f32 %0, %1;" : "=r"(o) : "f"(v));
    return __uint_as_float(o);
}
__device__ __forceinline__ void cp16(uint32_t dst, const void* src, int nbytes) {
    asm volatile("cp.async.cg.shared.global [%0], [%1], 16, %2;"
                 :: "r"(dst), "l"(src), "r"(nbytes));
}
#define CP_COMMIT() asm volatile("cp.async.commit_group;" ::: "memory")
#define CP_WAIT(n)  asm volatile("cp.async.wait_group %0;" :: "n"(n) : "memory")

// m16n8k8 tf32 MMA, fp32 accumulate (sm_80+ baseline PTX).
__device__ __forceinline__ void mma8(float& d0, float& d1, float& d2, float& d3,
                                     float a0, float a1, float a2, float a3,
                                     float b0, float b1) {
    asm volatile(
        "mma.sync.aligned.m16n8k8.row.col.f32.tf32.tf32.f32 "
        "{%0,%1,%2,%3}, {%4,%5,%6,%7}, {%8,%9}, {%0,%1,%2,%3};"
        : "+f"(d0), "+f"(d1), "+f"(d2), "+f"(d3)
        : "r"(__float_as_uint(a0)), "r"(__float_as_uint(a1)),
          "r"(__float_as_uint(a2)), "r"(__float_as_uint(a3)),
          "r"(__float_as_uint(b0)), "r"(__float_as_uint(b1)));
}

// ---------------------------------------------------------------------------
// SMEM layout (floats). k32 chunks, 3 stages:
//   A stage = 2 subtiles (k16 each) of [256 rows x 20 floats] (conflict-free)
//   B stage = [32 rows x 136 floats]                           (conflict-free)
// ---------------------------------------------------------------------------
#define A_STRIDE 20
#define SUB_SZ   (256 * A_STRIDE)       // 5120 floats per k16 subtile
#define A_SZ     (2 * SUB_SZ)           // 10240 floats / stage
#define B_STRIDE 136
#define B_SZ     (32 * B_STRIDE)        // 4352 floats / stage
#define STAGES   3
#define B_BASE   (STAGES * A_SZ)                    // 30720
#define SG_OFF   (B_BASE + STAGES * B_SZ)           // 43776
#define SB_OFF   (SG_OFF + 128)                     // 43904
#define IX_OFF   (SB_OFF + 128)                     // 44032
#define SMEM_FLOATS (IX_OFF + 256 * KTAPS)          // 46336
#define SMEM_BYTES  (SMEM_FLOATS * 4)               // 185344

// ===========================================================================
// Fused gather-GEMM (mma.sync tf32) + GroupNorm + ReLU.
// CTA: 256 sites x 128 out-channels, 16 warps (warp tile 64x32), k32 pipeline.
// 4 warps per SMSP for latency hiding; accumulation order identical to R4/R5.
// ===========================================================================
template<int CIN, bool ROUND_OUT>
__global__ __launch_bounds__(512, 1)
void spconv_mma(const float* __restrict__ X, const int* __restrict__ nbr,
                const float* __restrict__ W,       // [KTAPS*CIN, 512] row-major, tf32-rounded
                const float* __restrict__ gamma, const float* __restrict__ beta,
                float* __restrict__ Y)
{
    constexpr int KTOT = KTAPS * CIN;
    constexpr int NCH  = KTOT / 32;     // k-chunks of 32
    constexpr int CPT  = CIN / 32;      // chunks per tap (never crosses taps)

    extern __shared__ float sm[];
    const uint32_t smbase = smem_u32(sm);
    int* sidx = (int*)(sm + IX_OFF);

    const int tid = threadIdx.x;
    const int m0  = blockIdx.x * 256;
    const int n0  = blockIdx.y * 128;

    for (int i = tid; i < 128; i += 512) {
        sm[SG_OFF + i] = gamma[n0 + i];
        sm[SB_OFF + i] = beta[n0 + i];
    }
    for (int i = tid; i < 256 * KTAPS; i += 512)
        sidx[i] = nbr[(size_t)m0 * KTAPS + i];
    __syncthreads();

    const int warp = tid >> 5, lane = tid & 31;
    const int wm  = (warp >> 2) * 64;   // warp M offset: 0,64,128,192
    const int wn  = (warp & 3) * 32;    // warp N offset: 0,32,64,96
    const int gid = lane >> 2;          // 0..7
    const int q   = lane & 3;           // 0..3

    float d[4][4][4];                   // [mt][nt][reg] — 64 accumulators
    #pragma unroll
    for (int i = 0; i < 4; i++)
        #pragma unroll
        for (int j = 0; j < 4; j++)
            #pragma unroll
            for (int r = 0; r < 4; r++) d[i][j][r] = 0.f;

    // ---- async load of one k32 chunk into stage s (512 threads) ----
    auto load_chunk = [&](int ch, int s) {
        const int tap = ch / CPT;
        const int c0  = (ch - tap * CPT) * 32;
        const uint32_t abase = smbase + (uint32_t)s * (A_SZ * 4);
        #pragma unroll
        for (int t = 0; t < 4; t++) {               // 2048 A granules (256 rows x 8)
            const int g   = tid + (t << 9);
            const int row = g >> 3, kq = g & 7;
            const int sub = kq >> 2, kk = kq & 3;
            const int nid = sidx[row * KTAPS + tap];
            const float* src = X + (size_t)(nid < 0 ? 0 : nid) * CIN + c0 + kq * 4;
            cp16(abase + (uint32_t)(sub * (SUB_SZ * 4) + row * 80 + kk * 16),
                 src, nid < 0 ? 0 : 16);
        }
        const uint32_t bbase = smbase + (uint32_t)(B_BASE * 4) + (uint32_t)s * (B_SZ * 4);
        const float* wb = W + (size_t)ch * 32 * HID + n0;
        #pragma unroll
        for (int t = 0; t < 2; t++) {               // 1024 B granules (32 rows x 32)
            const int g  = tid + (t << 9);
            const int kr = g >> 5, ns = g & 31;
            cp16(bbase + (uint32_t)(kr * 544 + ns * 16), wb + (size_t)kr * HID + ns * 4, 16);
        }
    };

    // ---- compute one k32 chunk from stage s (4 k8 steps; same k order as R4/R5) ----
    auto compute = [&](int s) {
        const float* Astage = sm + s * A_SZ;
        const float* Bf     = sm + B_BASE + s * B_SZ;
        #pragma unroll
        for (int k8 = 0; k8 < 4; k8++) {
            const float* Af = Astage + (k8 >> 1) * SUB_SZ;
            const int c = (k8 & 1) * 8 + q;
            const int k = k8 * 8 + q;
            float a[4][4];
            #pragma unroll
            for (int mt = 0; mt < 4; mt++) {
                const int r = wm + mt * 16 + gid;
                a[mt][0] = Af[r * A_STRIDE + c];
                a[mt][1] = Af[(r + 8) * A_STRIDE + c];
                a[mt][2] = Af[r * A_STRIDE + c + 4];
                a[mt][3] = Af[(r + 8) * A_STRIDE + c + 4];
            }
            #pragma unroll
            for (int nt = 0; nt < 4; nt++) {
                const int n = wn + nt * 8 + gid;
                const float b0 = Bf[k * B_STRIDE + n];
                const float b1 = Bf[(k + 4) * B_STRIDE + n];
                #pragma unroll
                for (int mt = 0; mt < 4; mt++)
                    mma8(d[mt][nt][0], d[mt][nt][1], d[mt][nt][2], d[mt][nt][3],
                         a[mt][0], a[mt][1], a[mt][2], a[mt][3], b0, b1);
            }
        }
    };

    // ---- 3-stage pipelined mainloop (one barrier per k32 chunk) ----
    load_chunk(0, 0); CP_COMMIT();
    load_chunk(1, 1); CP_COMMIT();
    #pragma unroll 1
    for (int ch = 0; ch < NCH; ch++) {
        CP_WAIT(1);                     // stage ch resident (this thread)
        __syncthreads();                // visible to all; stage (ch-1)%3 free
        if (ch + 2 < NCH) load_chunk(ch + 2, (ch + 2) % STAGES);
        CP_COMMIT();
        compute(ch % STAGES);
    }

    // ---- fused GroupNorm(16-ch groups) + ReLU epilogue ----
    // Warp tile 64x32 = 2 groups of 16 channels per row-fragment.
    #pragma unroll
    for (int mt = 0; mt < 4; mt++) {
        #pragma unroll
        for (int h = 0; h < 2; h++) {
            const int row = m0 + wm + mt * 16 + gid + h * 8;
            float* yr = Y + (size_t)row * HID + n0 + wn;
            #pragma unroll
            for (int g = 0; g < 2; g++) {
                const float v0 = d[mt][2 * g    ][2 * h];
                const float v1 = d[mt][2 * g    ][2 * h + 1];
                const float v2 = d[mt][2 * g + 1][2 * h];
                const float v3 = d[mt][2 * g + 1][2 * h + 1];
                float s  = v0 + v1 + v2 + v3;
                float ss = v0 * v0 + v1 * v1 + v2 * v2 + v3 * v3;
                s  += __shfl_xor_sync(0xffffffffu, s, 1);
                ss += __shfl_xor_sync(0xffffffffu, ss, 1);
                s  += __shfl_xor_sync(0xffffffffu, s, 2);
                ss += __shfl_xor_sync(0xffffffffu, ss, 2);
                const float mu  = s * (1.f / 16.f);
                const float var = ss * (1.f / 16.f) - mu * mu;
                const float rs  = rsqrtf(var + EPS);
                const int cb = wn + 16 * g + 2 * q;       // gamma/beta index in [0,128)
                float o0 = fmaxf(fmaf((v0 - mu) * rs, sm[SG_OFF + cb],     sm[SB_OFF + cb]),     0.f);
                float o1 = fmaxf(fmaf((v1 - mu) * rs, sm[SG_OFF + cb + 1], sm[SB_OFF + cb + 1]), 0.f);
                float o2 = fmaxf(fmaf((v2 - mu) * rs, sm[SG_OFF + cb + 8], sm[SB_OFF + cb + 8]), 0.f);
                float o3 = fmaxf(fmaf((v3 - mu) * rs, sm[SG_OFF + cb + 9], sm[SB_OFF + cb + 9]), 0.f);
                if (ROUND_OUT) {
                    o0 = tf32_rn(o0); o1 = tf32_rn(o1);
                    o2 = tf32_rn(o2); o3 = tf32_rn(o3);
                }
                *(float2*)(yr + 16 * g + 2 * q)     = make_float2(o0, o1);
                *(float2*)(yr + 16 * g + 8 + 2 * q) = make_float2(o2, o3);
            }
        }
    }
}

// ---------------------------------------------------------------------------
// tf32-RNA rounding copy (float4 per thread)
// ---------------------------------------------------------------------------
__global__ void round_copy(const float* __restrict__ src, float* __restrict__ dst, int n4)
{
    const int t = blockIdx.x * blockDim.x + threadIdx.x;
    if (t >= n4) return;
    float4 v = ((const float4*)src)[t];
    v.x = tf32_rn(v.x); v.y = tf32_rn(v.y);
    v.z = tf32_rn(v.z); v.w = tf32_rn(v.w);
    ((float4*)dst)[t] = v;
}

// ===========================================================================
// kernel_launch: prep (round) + 8 fused layers, ping-pong buffers.
// ===========================================================================
extern "C" void kernel_launch(void* const* d_in, const int* in_sizes, int n_in,
                              void* d_out, int out_size)
{
    const float* feat  = (const float*)d_in[0];   // [131072, 256]
    const int*   nbr   = (const int*)  d_in[1];   // [131072, 9]
    const float* w0    = (const float*)d_in[2];   // [2304, 512]
    const float* wrest = (const float*)d_in[3];   // [7, 4608, 512]
    const float* gamma = (const float*)d_in[4];   // [8, 512]
    const float* beta  = (const float*)d_in[5];   // [8, 512]
    float* out = (float*)d_out;

    float *bufA, *bufB, *featr, *Wr;
    cudaGetSymbolAddress((void**)&bufA, g_bufA);
    cudaGetSymbolAddress((void**)&bufB, g_bufB);
    cudaGetSymbolAddress((void**)&featr, g_featr);
    cudaGetSymbolAddress((void**)&Wr, g_W);

    cudaFuncSetAttribute(spconv_mma<256, true>,
                         cudaFuncAttributeMaxDynamicSharedMemorySize, SMEM_BYTES);
    cudaFuncSetAttribute(spconv_mma<512, true>,
                         cudaFuncAttributeMaxDynamicSharedMemorySize, SMEM_BYTES);
    cudaFuncSetAttribute(spconv_mma<512, false>,
                         cudaFuncAttributeMaxDynamicSharedMemorySize, SMEM_BYTES);

    // Pre-round features + all weights to tf32 (RNA) so HW truncation is exact.
    {
        const int f4 = NSITES * 256 / 4;
        round_copy<<<(f4 + 255) / 256, 256>>>(feat, featr, f4);
        const int w04 = (int)(W0_ELEMS / 4);
        round_copy<<<(w04 + 255) / 256, 256>>>(w0, Wr, w04);
        const int wl4 = (int)(7 * WL_ELEMS / 4);
        round_copy<<<(wl4 + 255) / 256, 256>>>(wrest, Wr + W0_ELEMS, wl4);
    }

    const dim3 grid(NSITES / 256, HID / 128);     // 512 x 4

    // layer 0: CIN=256
    spconv_mma<256, true><<<grid, 512, SMEM_BYTES>>>(featr, nbr, Wr, gamma, beta, bufA);

    const float* x = bufA;
    float*       y = bufB;
    for (int l = 1; l < 8; l++) {
        const float* wl = Wr + W0_ELEMS + (size_t)(l - 1) * WL_ELEMS;
        if (l == 7)
            spconv_mma<512, false><<<grid, 512, SMEM_BYTES>>>(
                x, nbr, wl, gamma + l * HID, beta + l * HID, out);
        else
            spconv_mma<512, true><<<grid, 512, SMEM_BYTES>>>(
                x, nbr, wl, gamma + l * HID, beta + l * HID, y);
        x = y;
        y = (y == bufB) ? bufA : bufB;
    }
}

// round 7
// speedup vs baseline: 1.1623x; 1.1623x over previous
#include <cuda_runtime.h>
#include <cuda_fp16.h>
#include <cstdint>
#include <cstddef>

#define NSITES 131072
#define HID    512
#define KTAPS  9
#define EPS    1e-5f

// ---------------------------------------------------------------------------
// Device-global scratch (allocation-free rule)
// ---------------------------------------------------------------------------
__device__ __align__(16) __half g_actA[(size_t)NSITES * HID];
__device__ __align__(16) __half g_actB[(size_t)NSITES * HID];
__device__ __align__(16) __half g_featH[(size_t)NSITES * 256];
// Wp layout per layer: [chunk(k32)][h(2)][n(512)][k(32)] fp16
#define W0H ((size_t)72  * 32768)      // 72 chunks  (K=2304)
#define WLH ((size_t)144 * 32768)      // 144 chunks (K=4608)
__device__ __align__(16) __half g_Wp[W0H + 7 * WLH];

// ---------------------------------------------------------------------------
// Helpers (baseline PTX only — must pass ptxas at .target sm_103)
// ---------------------------------------------------------------------------
__device__ __forceinline__ uint32_t smem_u32(const void* p) {
    uint32_t a;
    asm("{ .reg .u64 t; cvta.to.shared.u64 t, %1; cvt.u32.u64 %0, t; }" : "=r"(a) : "l"(p));
    return a;
}
__device__ __forceinline__ void cp16(uint32_t dst, const void* src, int nbytes) {
    asm volatile("cp.async.cg.shared.global [%0], [%1], 16, %2;"
                 :: "r"(dst), "l"(src), "r"(nbytes));
}
#define CP_COMMIT() asm volatile("cp.async.commit_group;" ::: "memory")
#define CP_WAIT(n)  asm volatile("cp.async.wait_group %0;" :: "n"(n) : "memory")

__device__ __forceinline__ void ldmx4(uint32_t* r, uint32_t addr) {
    asm volatile("ldmatrix.sync.aligned.m8n8.x4.shared.b16 {%0,%1,%2,%3}, [%4];"
                 : "=r"(r[0]), "=r"(r[1]), "=r"(r[2]), "=r"(r[3]) : "r"(addr));
}
// m16n8k16 fp16 MMA, fp32 accumulate (sm_80 baseline PTX).
__device__ __forceinline__ void mma16(float* d, const uint32_t* a, const uint32_t* b) {
    asm volatile(
        "mma.sync.aligned.m16n8k16.row.col.f32.f16.f16.f32 "
        "{%0,%1,%2,%3}, {%4,%5,%6,%7}, {%8,%9}, {%0,%1,%2,%3};"
        : "+f"(d[0]), "+f"(d[1]), "+f"(d[2]), "+f"(d[3])
        : "r"(a[0]), "r"(a[1]), "r"(a[2]), "r"(a[3]), "r"(b[0]), "r"(b[1]));
}

// ---------------------------------------------------------------------------
// SMEM layout (bytes). Per stage: A tile 256 rows x 80B, B tile 256 rows x 80B
// (B rows = [h(2) x 128 n], each row holds k32 = 64B + 16B pad).
// Row stride 80B => ldmatrix 8-address groups hit distinct bank quads.
// ---------------------------------------------------------------------------
#define ROW_B    80
#define A_SZB    (256 * ROW_B)          // 20480
#define STAGE_B  (2 * A_SZB)            // 40960 (A then B)
#define STAGES   3
#define SGB      (STAGES * STAGE_B)     // 122880: gamma (128 f32)
#define SBB      (SGB + 512)            // beta
#define IXB      (SBB + 512)            // 256*9 int32 = 9216
#define SMEM_BYTES (IXB + 9216)         // 132608

// ===========================================================================
// Fused gather-GEMM (mma.sync fp16, split weights, fp32 acc) + GroupNorm + ReLU
// CTA: 256 sites x 128 out-ch, 8 warps (warp tile 64x64), k32 3-stage pipeline.
// ===========================================================================
template<int CIN, bool LAST>
__global__ __launch_bounds__(256, 1)
void spconv_h(const __half* __restrict__ X, const int* __restrict__ nbr,
              const __half* __restrict__ Wp,     // [ch][2][512][32] fp16
              const float* __restrict__ gamma, const float* __restrict__ beta,
              void* __restrict__ Yv)
{
    constexpr int KTOT = KTAPS * CIN;
    constexpr int NCH  = KTOT / 32;
    constexpr int CPT  = CIN / 32;

    extern __shared__ char smc[];
    const uint32_t smbase = smem_u32(smc);
    float* sgam = (float*)(smc + SGB);
    float* sbet = (float*)(smc + SBB);
    int*   sidx = (int*)  (smc + IXB);

    const int tid = threadIdx.x;
    const int m0  = blockIdx.x * 256;
    const int n0  = blockIdx.y * 128;

    for (int i = tid; i < 128; i += 256) {
        sgam[i] = gamma[n0 + i];
        sbet[i] = beta[n0 + i];
    }
    for (int i = tid; i < 256 * KTAPS; i += 256)
        sidx[i] = nbr[(size_t)m0 * KTAPS + i];
    __syncthreads();

    const int warp = tid >> 5, lane = tid & 31;
    const int wm  = (warp >> 1) * 64;
    const int wn  = (warp & 1) * 64;
    const int gid = lane >> 2;
    const int q   = lane & 3;

    // per-thread ldmatrix address components
    const int a_off = (lane & 15) * ROW_B + (lane >> 4) * 16;                    // A lane term
    const int b_off = ((lane & 7) + ((lane >> 4) & 1) * 8) * ROW_B + ((lane >> 3) & 1) * 16;

    float d[4][8][4];
    #pragma unroll
    for (int i = 0; i < 4; i++)
        #pragma unroll
        for (int j = 0; j < 8; j++)
            #pragma unroll
            for (int r = 0; r < 4; r++) d[i][j][r] = 0.f;

    // ---- async load of one k32 chunk into stage s ----
    auto load_chunk = [&](int ch, int s) {
        const int tap = ch / CPT;
        const int c0  = (ch - tap * CPT) * 32;                 // fp16 elems
        const uint32_t abase = smbase + (uint32_t)s * STAGE_B;
        #pragma unroll
        for (int t = 0; t < 4; t++) {               // A: 1024 granules (256 rows x 4)
            const int g   = tid + (t << 8);
            const int row = g >> 2, seg = g & 3;
            const int nid = sidx[row * KTAPS + tap];
            const __half* src = X + (size_t)(nid < 0 ? 0 : nid) * CIN + c0 + seg * 8;
            cp16(abase + (uint32_t)(row * ROW_B + seg * 16), src, nid < 0 ? 0 : 16);
        }
        const uint32_t bbase = abase + A_SZB;
        const __half* wc = Wp + (size_t)ch * 32768;
        #pragma unroll
        for (int t = 0; t < 4; t++) {               // B: 1024 granules (256 rows x 4)
            const int g   = tid + (t << 8);
            const int row = g >> 2, seg = g & 3;    // row = h*128 + nl
            const int h   = row >> 7, nl = row & 127;
            const __half* src = wc + (size_t)h * 16384 + (size_t)(n0 + nl) * 32 + seg * 8;
            cp16(bbase + (uint32_t)(row * ROW_B + seg * 16), src, 16);
        }
    };

    // ---- compute one k32 chunk from stage s (2 k16 steps) ----
    auto compute = [&](int s) {
        const uint32_t abase = smbase + (uint32_t)s * STAGE_B;
        const uint32_t bbase = abase + A_SZB;
        #pragma unroll
        for (int s16 = 0; s16 < 2; s16++) {
            uint32_t a[4][4];
            #pragma unroll
            for (int mt = 0; mt < 4; mt++)
                ldmx4(a[mt], abase + (uint32_t)((wm + mt * 16) * ROW_B + s16 * 32 + a_off));
            #pragma unroll
            for (int h = 0; h < 2; h++) {
                uint32_t b[8][2];
                #pragma unroll
                for (int np = 0; np < 4; np++) {
                    uint32_t r[4];
                    ldmx4(r, bbase + (uint32_t)((h * 128 + wn + np * 16) * ROW_B
                                                + s16 * 32 + b_off));
                    b[2 * np][0] = r[0]; b[2 * np][1] = r[1];
                    b[2 * np + 1][0] = r[2]; b[2 * np + 1][1] = r[3];
                }
                #pragma unroll
                for (int nt = 0; nt < 8; nt++)
                    #pragma unroll
                    for (int mt = 0; mt < 4; mt++)
                        mma16(d[mt][nt], a[mt], b[nt]);
            }
        }
    };

    // ---- 3-stage pipelined mainloop ----
    load_chunk(0, 0); CP_COMMIT();
    load_chunk(1, 1); CP_COMMIT();
    #pragma unroll 1
    for (int ch = 0; ch < NCH; ch++) {
        CP_WAIT(1);
        __syncthreads();
        if (ch + 2 < NCH) load_chunk(ch + 2, (ch + 2) % STAGES);
        CP_COMMIT();
        compute(ch % STAGES);
    }

    // ---- fused GroupNorm(16-ch groups) + ReLU epilogue ----
    float* Yf = (float*)Yv;
    __half* Yh = (__half*)Yv;
    #pragma unroll
    for (int mt = 0; mt < 4; mt++) {
        #pragma unroll
        for (int h = 0; h < 2; h++) {
            const int row = m0 + wm + mt * 16 + gid + h * 8;
            const size_t rb = (size_t)row * HID + n0 + wn;
            #pragma unroll
            for (int g = 0; g < 4; g++) {
                const float v0 = d[mt][2 * g    ][2 * h];
                const float v1 = d[mt][2 * g    ][2 * h + 1];
                const float v2 = d[mt][2 * g + 1][2 * h];
                const float v3 = d[mt][2 * g + 1][2 * h + 1];
                float s  = v0 + v1 + v2 + v3;
                float ss = v0 * v0 + v1 * v1 + v2 * v2 + v3 * v3;
                s  += __shfl_xor_sync(0xffffffffu, s, 1);
                ss += __shfl_xor_sync(0xffffffffu, ss, 1);
                s  += __shfl_xor_sync(0xffffffffu, s, 2);
                ss += __shfl_xor_sync(0xffffffffu, ss, 2);
                const float mu  = s * (1.f / 16.f);
                const float var = ss * (1.f / 16.f) - mu * mu;
                const float rs  = rsqrtf(var + EPS);
                const int cb = wn + 16 * g + 2 * q;         // gamma/beta index in [0,128)
                const float o0 = fmaxf(fmaf((v0 - mu) * rs, sgam[cb],     sbet[cb]),     0.f);
                const float o1 = fmaxf(fmaf((v1 - mu) * rs, sgam[cb + 1], sbet[cb + 1]), 0.f);
                const float o2 = fmaxf(fmaf((v2 - mu) * rs, sgam[cb + 8], sbet[cb + 8]), 0.f);
                const float o3 = fmaxf(fmaf((v3 - mu) * rs, sgam[cb + 9], sbet[cb + 9]), 0.f);
                if (LAST) {
                    *(float2*)(Yf + rb + 16 * g + 2 * q)     = make_float2(o0, o1);
                    *(float2*)(Yf + rb + 16 * g + 8 + 2 * q) = make_float2(o2, o3);
                } else {
                    *(__half2*)(Yh + rb + 16 * g + 2 * q)     = __floats2half2_rn(o0, o1);
                    *(__half2*)(Yh + rb + 16 * g + 8 + 2 * q) = __floats2half2_rn(o2, o3);
                }
            }
        }
    }
}

// ---------------------------------------------------------------------------
// Prep: weight transpose + hi/lo fp16 split.
// W [R,512] fp32 -> Wp [R/32][2][512][32] fp16.  grid (16, R/32), block (32,8).
// ---------------------------------------------------------------------------
__global__ void w_split(const float* __restrict__ W, __half* __restrict__ Wp)
{
    __shared__ float t[32][33];
    const int bx = blockIdx.x;      // n tile
    const int by = blockIdx.y;      // k chunk
    const int x = threadIdx.x, y = threadIdx.y;
    #pragma unroll
    for (int i = 0; i < 32; i += 8)
        t[y + i][x] = W[(size_t)(by * 32 + y + i) * 512 + bx * 32 + x];
    __syncthreads();
    #pragma unroll
    for (int i = 0; i < 32; i += 8) {
        const int nl = y + i, kk = x;
        const float w = t[kk][nl];
        const __half h0 = __float2half_rn(w);
        const __half h1 = __float2half_rn(w - __half2float(h0));
        const size_t base = (size_t)by * 32768 + (size_t)(bx * 32 + nl) * 32 + kk;
        Wp[base]         = h0;
        Wp[base + 16384] = h1;
    }
}

// Features fp32 -> fp16 (8 elems/thread)
__global__ void f2h(const float* __restrict__ src, __half* __restrict__ dst)
{
    const int t = blockIdx.x * blockDim.x + threadIdx.x;
    const float4* s = (const float4*)src + 2 * (size_t)t;
    const float4 v0 = s[0], v1 = s[1];
    __half2* o = (__half2*)dst + 4 * (size_t)t;
    o[0] = __floats2half2_rn(v0.x, v0.y);
    o[1] = __floats2half2_rn(v0.z, v0.w);
    o[2] = __floats2half2_rn(v1.x, v1.y);
    o[3] = __floats2half2_rn(v1.z, v1.w);
}

// ===========================================================================
// kernel_launch: prep + 8 fused layers, ping-pong fp16 activations.
// ===========================================================================
extern "C" void kernel_launch(void* const* d_in, const int* in_sizes, int n_in,
                              void* d_out, int out_size)
{
    const float* feat  = (const float*)d_in[0];   // [131072, 256]
    const int*   nbr   = (const int*)  d_in[1];   // [131072, 9]
    const float* w0    = (const float*)d_in[2];   // [2304, 512]
    const float* wrest = (const float*)d_in[3];   // [7, 4608, 512]
    const float* gamma = (const float*)d_in[4];   // [8, 512]
    const float* beta  = (const float*)d_in[5];   // [8, 512]

    __half *actA, *actB, *featH, *Wp;
    cudaGetSymbolAddress((void**)&actA, g_actA);
    cudaGetSymbolAddress((void**)&actB, g_actB);
    cudaGetSymbolAddress((void**)&featH, g_featH);
    cudaGetSymbolAddress((void**)&Wp, g_Wp);

    cudaFuncSetAttribute(spconv_h<256, false>,
                         cudaFuncAttributeMaxDynamicSharedMemorySize, SMEM_BYTES);
    cudaFuncSetAttribute(spconv_h<512, false>,
                         cudaFuncAttributeMaxDynamicSharedMemorySize, SMEM_BYTES);
    cudaFuncSetAttribute(spconv_h<512, true>,
                         cudaFuncAttributeMaxDynamicSharedMemorySize, SMEM_BYTES);

    // Prep: fp16 features + split/transposed fp16 weights
    f2h<<<(NSITES * 256 / 8) / 256, 256>>>(feat, featH);
    w_split<<<dim3(16, 72), dim3(32, 8)>>>(w0, Wp);
    for (int l = 0; l < 7; l++)
        w_split<<<dim3(16, 144), dim3(32, 8)>>>(
            wrest + (size_t)l * 4608 * 512, Wp + W0H + (size_t)l * WLH);

    const dim3 grid(NSITES / 256, HID / 128);     // 512 x 4

    // layer 0: CIN=256
    spconv_h<256, false><<<grid, 256, SMEM_BYTES>>>(featH, nbr, Wp, gamma, beta, actA);

    const __half* x = actA;
    __half*       y = actB;
    for (int l = 1; l < 8; l++) {
        const __half* wl = Wp + W0H + (size_t)(l - 1) * WLH;
        if (l == 7)
            spconv_h<512, true><<<grid, 256, SMEM_BYTES>>>(
                x, nbr, wl, gamma + l * HID, beta + l * HID, d_out);
        else
            spconv_h<512, false><<<grid, 256, SMEM_BYTES>>>(
                x, nbr, wl, gamma + l * HID, beta + l * HID, y);
        x = y;
        y = (y == actB) ? actA : actB;
    }
}

// round 8
// speedup vs baseline: 1.8626x; 1.6026x over previous
#include <cuda_runtime.h>
#include <cuda_fp16.h>
#include <cstdint>
#include <cstddef>

#define NSITES 131072
#define HID    512
#define KTAPS  9
#define EPS    1e-5f

// ---------------------------------------------------------------------------
// Device-global scratch (allocation-free rule)
// ---------------------------------------------------------------------------
__device__ __align__(16) __half g_actA[(size_t)NSITES * HID];
__device__ __align__(16) __half g_actB[(size_t)NSITES * HID];
__device__ __align__(16) __half g_featH[(size_t)NSITES * 256];
// Wp layout per layer: [chunk(k32)][n(512)][k(32)] fp16 (hi only)
#define W0H ((size_t)72  * 16384)      // 72 chunks  (K=2304)
#define WLH ((size_t)144 * 16384)      // 144 chunks (K=4608)
__device__ __align__(16) __half g_Wp[W0H + 7 * WLH];

// ---------------------------------------------------------------------------
// Helpers (baseline PTX only — must pass ptxas at .target sm_103)
// ---------------------------------------------------------------------------
__device__ __forceinline__ uint32_t smem_u32(const void* p) {
    uint32_t a;
    asm("{ .reg .u64 t; cvta.to.shared.u64 t, %1; cvt.u32.u64 %0, t; }" : "=r"(a) : "l"(p));
    return a;
}
__device__ __forceinline__ void cp16(uint32_t dst, const void* src, int nbytes) {
    asm volatile("cp.async.cg.shared.global [%0], [%1], 16, %2;"
                 :: "r"(dst), "l"(src), "r"(nbytes));
}
#define CP_COMMIT() asm volatile("cp.async.commit_group;" ::: "memory")
#define CP_WAIT(n)  asm volatile("cp.async.wait_group %0;" :: "n"(n) : "memory")

__device__ __forceinline__ void ldmx4(uint32_t* r, uint32_t addr) {
    asm volatile("ldmatrix.sync.aligned.m8n8.x4.shared.b16 {%0,%1,%2,%3}, [%4];"
                 : "=r"(r[0]), "=r"(r[1]), "=r"(r[2]), "=r"(r[3]) : "r"(addr));
}
// m16n8k16 fp16 MMA, fp32 accumulate (sm_80 baseline PTX).
__device__ __forceinline__ void mma16(float* d, const uint32_t* a, const uint32_t* b) {
    asm volatile(
        "mma.sync.aligned.m16n8k16.row.col.f32.f16.f16.f32 "
        "{%0,%1,%2,%3}, {%4,%5,%6,%7}, {%8,%9}, {%0,%1,%2,%3};"
        : "+f"(d[0]), "+f"(d[1]), "+f"(d[2]), "+f"(d[3])
        : "r"(a[0]), "r"(a[1]), "r"(a[2]), "r"(a[3]), "r"(b[0]), "r"(b[1]));
}

// ---------------------------------------------------------------------------
// SMEM layout (bytes). Per stage: A = 256 rows x 80B, B = 128 rows x 80B.
// Row stride 80B => ldmatrix 8-address groups hit distinct bank quads.
// ---------------------------------------------------------------------------
#define ROW_B    80
#define A_SZB    (256 * ROW_B)          // 20480
#define B_SZB    (128 * ROW_B)          // 10240
#define STAGE_B  (A_SZB + B_SZB)        // 30720
#define STAGES   3
#define SGB      (STAGES * STAGE_B)     // 92160: gamma (128 f32)
#define SBB      (SGB + 512)            // beta
#define IXB      (SBB + 512)            // 256*9 int32 = 9216
#define SMEM_BYTES (IXB + 9216)         // 101888

// ===========================================================================
// Fused gather-GEMM (single mma.sync fp16, fp32 acc) + GroupNorm + ReLU
// CTA: 256 sites x 128 out-ch, 8 warps (warp tile 64x64), k32 3-stage pipeline.
// ===========================================================================
template<int CIN, bool LAST>
__global__ __launch_bounds__(256, 1)
void spconv_h(const __half* __restrict__ X, const int* __restrict__ nbr,
              const __half* __restrict__ Wp,     // [ch][512][32] fp16
              const float* __restrict__ gamma, const float* __restrict__ beta,
              void* __restrict__ Yv)
{
    constexpr int KTOT = KTAPS * CIN;
    constexpr int NCH  = KTOT / 32;
    constexpr int CPT  = CIN / 32;

    extern __shared__ char smc[];
    const uint32_t smbase = smem_u32(smc);
    float* sgam = (float*)(smc + SGB);
    float* sbet = (float*)(smc + SBB);
    int*   sidx = (int*)  (smc + IXB);

    const int tid = threadIdx.x;
    const int m0  = blockIdx.x * 256;
    const int n0  = blockIdx.y * 128;

    for (int i = tid; i < 128; i += 256) {
        sgam[i] = gamma[n0 + i];
        sbet[i] = beta[n0 + i];
    }
    for (int i = tid; i < 256 * KTAPS; i += 256)
        sidx[i] = nbr[(size_t)m0 * KTAPS + i];
    __syncthreads();

    const int warp = tid >> 5, lane = tid & 31;
    const int wm  = (warp >> 1) * 64;
    const int wn  = (warp & 1) * 64;
    const int gid = lane >> 2;
    const int q   = lane & 3;

    // per-thread ldmatrix address components
    const int a_off = (lane & 15) * ROW_B + (lane >> 4) * 16;
    const int b_off = ((lane & 7) + ((lane >> 4) & 1) * 8) * ROW_B + ((lane >> 3) & 1) * 16;

    float d[4][8][4];
    #pragma unroll
    for (int i = 0; i < 4; i++)
        #pragma unroll
        for (int j = 0; j < 8; j++)
            #pragma unroll
            for (int r = 0; r < 4; r++) d[i][j][r] = 0.f;

    // ---- async load of one k32 chunk into stage s ----
    auto load_chunk = [&](int ch, int s) {
        const int tap = ch / CPT;
        const int c0  = (ch - tap * CPT) * 32;                 // fp16 elems
        const uint32_t abase = smbase + (uint32_t)s * STAGE_B;
        #pragma unroll
        for (int t = 0; t < 4; t++) {               // A: 1024 granules (256 rows x 4)
            const int g   = tid + (t << 8);
            const int row = g >> 2, seg = g & 3;
            const int nid = sidx[row * KTAPS + tap];
            const __half* src = X + (size_t)(nid < 0 ? 0 : nid) * CIN + c0 + seg * 8;
            cp16(abase + (uint32_t)(row * ROW_B + seg * 16), src, nid < 0 ? 0 : 16);
        }
        const uint32_t bbase = abase + A_SZB;
        const __half* wc = Wp + (size_t)ch * 16384;
        #pragma unroll
        for (int t = 0; t < 2; t++) {               // B: 512 granules (128 rows x 4)
            const int g   = tid + (t << 8);
            const int nl  = g >> 2, seg = g & 3;
            const __half* src = wc + (size_t)(n0 + nl) * 32 + seg * 8;
            cp16(bbase + (uint32_t)(nl * ROW_B + seg * 16), src, 16);
        }
    };

    // ---- compute one k32 chunk from stage s (2 k16 steps, 64 MMAs/warp) ----
    auto compute = [&](int s) {
        const uint32_t abase = smbase + (uint32_t)s * STAGE_B;
        const uint32_t bbase = abase + A_SZB;
        #pragma unroll
        for (int s16 = 0; s16 < 2; s16++) {
            uint32_t a[4][4];
            #pragma unroll
            for (int mt = 0; mt < 4; mt++)
                ldmx4(a[mt], abase + (uint32_t)((wm + mt * 16) * ROW_B + s16 * 32 + a_off));
            uint32_t b[8][2];
            #pragma unroll
            for (int np = 0; np < 4; np++) {
                uint32_t r[4];
                ldmx4(r, bbase + (uint32_t)((wn + np * 16) * ROW_B + s16 * 32 + b_off));
                b[2 * np][0] = r[0];     b[2 * np][1] = r[1];
                b[2 * np + 1][0] = r[2]; b[2 * np + 1][1] = r[3];
            }
            #pragma unroll
            for (int nt = 0; nt < 8; nt++)
                #pragma unroll
                for (int mt = 0; mt < 4; mt++)
                    mma16(d[mt][nt], a[mt], b[nt]);
        }
    };

    // ---- 3-stage pipelined mainloop ----
    load_chunk(0, 0); CP_COMMIT();
    load_chunk(1, 1); CP_COMMIT();
    #pragma unroll 1
    for (int ch = 0; ch < NCH; ch++) {
        CP_WAIT(1);
        __syncthreads();
        if (ch + 2 < NCH) load_chunk(ch + 2, (ch + 2) % STAGES);
        CP_COMMIT();
        compute(ch % STAGES);
    }

    // ---- fused GroupNorm(16-ch groups) + ReLU epilogue ----
    float* Yf = (float*)Yv;
    __half* Yh = (__half*)Yv;
    #pragma unroll
    for (int mt = 0; mt < 4; mt++) {
        #pragma unroll
        for (int h = 0; h < 2; h++) {
            const int row = m0 + wm + mt * 16 + gid + h * 8;
            const size_t rb = (size_t)row * HID + n0 + wn;
            #pragma unroll
            for (int g = 0; g < 4; g++) {
                const float v0 = d[mt][2 * g    ][2 * h];
                const float v1 = d[mt][2 * g    ][2 * h + 1];
                const float v2 = d[mt][2 * g + 1][2 * h];
                const float v3 = d[mt][2 * g + 1][2 * h + 1];
                float s  = v0 + v1 + v2 + v3;
                float ss = v0 * v0 + v1 * v1 + v2 * v2 + v3 * v3;
                s  += __shfl_xor_sync(0xffffffffu, s, 1);
                ss += __shfl_xor_sync(0xffffffffu, ss, 1);
                s  += __shfl_xor_sync(0xffffffffu, s, 2);
                ss += __shfl_xor_sync(0xffffffffu, ss, 2);
                const float mu  = s * (1.f / 16.f);
                const float var = ss * (1.f / 16.f) - mu * mu;
                const float rs  = rsqrtf(var + EPS);
                const int cb = wn + 16 * g + 2 * q;
                const float o0 = fmaxf(fmaf((v0 - mu) * rs, sgam[cb],     sbet[cb]),     0.f);
                const float o1 = fmaxf(fmaf((v1 - mu) * rs, sgam[cb + 1], sbet[cb + 1]), 0.f);
                const float o2 = fmaxf(fmaf((v2 - mu) * rs, sgam[cb + 8], sbet[cb + 8]), 0.f);
                const float o3 = fmaxf(fmaf((v3 - mu) * rs, sgam[cb + 9], sbet[cb + 9]), 0.f);
                if (LAST) {
                    *(float2*)(Yf + rb + 16 * g + 2 * q)     = make_float2(o0, o1);
                    *(float2*)(Yf + rb + 16 * g + 8 + 2 * q) = make_float2(o2, o3);
                } else {
                    *(__half2*)(Yh + rb + 16 * g + 2 * q)     = __floats2half2_rn(o0, o1);
                    *(__half2*)(Yh + rb + 16 * g + 8 + 2 * q) = __floats2half2_rn(o2, o3);
                }
            }
        }
    }
}

// ---------------------------------------------------------------------------
// Prep: weight transpose to fp16 (RN): W [R,512] fp32 -> Wp [R/32][512][32].
// grid (16, R/32), block (32,8).
// ---------------------------------------------------------------------------
__global__ void w_prep(const float* __restrict__ W, __half* __restrict__ Wp)
{
    __shared__ float t[32][33];
    const int bx = blockIdx.x;      // n tile
    const int by = blockIdx.y;      // k chunk
    const int x = threadIdx.x, y = threadIdx.y;
    #pragma unroll
    for (int i = 0; i < 32; i += 8)
        t[y + i][x] = W[(size_t)(by * 32 + y + i) * 512 + bx * 32 + x];
    __syncthreads();
    #pragma unroll
    for (int i = 0; i < 32; i += 8) {
        const int nl = y + i, kk = x;
        Wp[(size_t)by * 16384 + (size_t)(bx * 32 + nl) * 32 + kk] =
            __float2half_rn(t[kk][nl]);
    }
}

// Features fp32 -> fp16 (8 elems/thread)
__global__ void f2h(const float* __restrict__ src, __half* __restrict__ dst)
{
    const int t = blockIdx.x * blockDim.x + threadIdx.x;
    const float4* s = (const float4*)src + 2 * (size_t)t;
    const float4 v0 = s[0], v1 = s[1];
    __half2* o = (__half2*)dst + 4 * (size_t)t;
    o[0] = __floats2half2_rn(v0.x, v0.y);
    o[1] = __floats2half2_rn(v0.z, v0.w);
    o[2] = __floats2half2_rn(v1.x, v1.y);
    o[3] = __floats2half2_rn(v1.z, v1.w);
}

// ===========================================================================
// kernel_launch: prep + 8 fused layers, ping-pong fp16 activations.
// ===========================================================================
extern "C" void kernel_launch(void* const* d_in, const int* in_sizes, int n_in,
                              void* d_out, int out_size)
{
    const float* feat  = (const float*)d_in[0];   // [131072, 256]
    const int*   nbr   = (const int*)  d_in[1];   // [131072, 9]
    const float* w0    = (const float*)d_in[2];   // [2304, 512]
    const float* wrest = (const float*)d_in[3];   // [7, 4608, 512]
    const float* gamma = (const float*)d_in[4];   // [8, 512]
    const float* beta  = (const float*)d_in[5];   // [8, 512]

    __half *actA, *actB, *featH, *Wp;
    cudaGetSymbolAddress((void**)&actA, g_actA);
    cudaGetSymbolAddress((void**)&actB, g_actB);
    cudaGetSymbolAddress((void**)&featH, g_featH);
    cudaGetSymbolAddress((void**)&Wp, g_Wp);

    cudaFuncSetAttribute(spconv_h<256, false>,
                         cudaFuncAttributeMaxDynamicSharedMemorySize, SMEM_BYTES);
    cudaFuncSetAttribute(spconv_h<512, false>,
                         cudaFuncAttributeMaxDynamicSharedMemorySize, SMEM_BYTES);
    cudaFuncSetAttribute(spconv_h<512, true>,
                         cudaFuncAttributeMaxDynamicSharedMemorySize, SMEM_BYTES);

    // Prep: fp16 features + transposed fp16 weights
    f2h<<<(NSITES * 256 / 8) / 256, 256>>>(feat, featH);
    w_prep<<<dim3(16, 72), dim3(32, 8)>>>(w0, Wp);
    for (int l = 0; l < 7; l++)
        w_prep<<<dim3(16, 144), dim3(32, 8)>>>(
            wrest + (size_t)l * 4608 * 512, Wp + W0H + (size_t)l * WLH);

    const dim3 grid(NSITES / 256, HID / 128);     // 512 x 4

    // layer 0: CIN=256
    spconv_h<256, false><<<grid, 256, SMEM_BYTES>>>(featH, nbr, Wp, gamma, beta, actA);

    const __half* x = actA;
    __half*       y = actB;
    for (int l = 1; l < 8; l++) {
        const __half* wl = Wp + W0H + (size_t)(l - 1) * WLH;
        if (l == 7)
            spconv_h<512, true><<<grid, 256, SMEM_BYTES>>>(
                x, nbr, wl, gamma + l * HID, beta + l * HID, d_out);
        else
            spconv_h<512, false><<<grid, 256, SMEM_BYTES>>>(
                x, nbr, wl, gamma + l * HID, beta + l * HID, y);
        x = y;
        y = (y == actB) ? actA : actB;
    }
}

// round 9
// speedup vs baseline: 2.1160x; 1.1360x over previous
#include <cuda_runtime.h>
#include <cuda_fp16.h>
#include <cstdint>
#include <cstddef>

#define NSITES 131072
#define HID    512
#define KTAPS  9
#define EPS    1e-5f

// ---------------------------------------------------------------------------
// Device-global scratch (allocation-free rule)
// ---------------------------------------------------------------------------
__device__ __align__(16) __half g_actA[(size_t)NSITES * HID];
__device__ __align__(16) __half g_actB[(size_t)NSITES * HID];
__device__ __align__(16) __half g_featH[(size_t)NSITES * 256];
// Wp per layer: [cpos = c0*9+tap][n(512)][k(32)] fp16
#define W0H ((size_t)72  * 16384)
#define WLH ((size_t)144 * 16384)
__device__ __align__(16) __half g_Wp[W0H + 7 * WLH];

// ---------------------------------------------------------------------------
// Helpers (baseline PTX only — must pass ptxas at .target sm_103)
// ---------------------------------------------------------------------------
__device__ __forceinline__ uint32_t smem_u32(const void* p) {
    uint32_t a;
    asm("{ .reg .u64 t; cvta.to.shared.u64 t, %1; cvt.u32.u64 %0, t; }" : "=r"(a) : "l"(p));
    return a;
}
__device__ __forceinline__ void cp16(uint32_t dst, const void* src, int nbytes) {
    asm volatile("cp.async.cg.shared.global [%0], [%1], 16, %2;"
                 :: "r"(dst), "l"(src), "r"(nbytes));
}
#define CP_COMMIT() asm volatile("cp.async.commit_group;" ::: "memory")
#define CP_WAIT(n)  asm volatile("cp.async.wait_group %0;" :: "n"(n) : "memory")

__device__ __forceinline__ void ldmx4(uint32_t* r, uint32_t addr) {
    asm volatile("ldmatrix.sync.aligned.m8n8.x4.shared.b16 {%0,%1,%2,%3}, [%4];"
                 : "=r"(r[0]), "=r"(r[1]), "=r"(r[2]), "=r"(r[3]) : "r"(addr));
}
__device__ __forceinline__ void mma16(float* d, const uint32_t* a, const uint32_t* b) {
    asm volatile(
        "mma.sync.aligned.m16n8k16.row.col.f32.f16.f16.f32 "
        "{%0,%1,%2,%3}, {%4,%5,%6,%7}, {%8,%9}, {%0,%1,%2,%3};"
        : "+f"(d[0]), "+f"(d[1]), "+f"(d[2]), "+f"(d[3])
        : "r"(a[0]), "r"(a[1]), "r"(a[2]), "r"(a[3]), "r"(b[0]), "r"(b[1]));
}

// ---------------------------------------------------------------------------
// SMEM layout (bytes).
// A halo buffer: 528 data rows + zero row @528, 80B stride, double-buffered.
// B stage: 128 n-rows x 80B, 3 stages.
// aslot LUT: [tap][site] uint32 = slot*80.
// ---------------------------------------------------------------------------
#define A_ROW_B   80
#define ZSLOT     528
#define A_ROWS    530
#define A_BUF_B   (A_ROWS * A_ROW_B)      // 42400
#define B_OFF     (2 * A_BUF_B)           // 84800
#define B_STAGE_B (128 * A_ROW_B)         // 10240
#define ASL_OFF   (B_OFF + 3 * B_STAGE_B) // 115520
#define SG_OFF    (ASL_OFF + 9216)        // 124736
#define SB_OFF    (SG_OFF + 512)
#define SMEM_BYTES (SB_OFF + 512)         // 125760

// ===========================================================================
// Fused gather-GEMM (mma.sync fp16, fp32 acc) + GroupNorm + ReLU.
// CTA: 256 sites x 128 out-ch, 8 warps (warp tile 64x64).
// K loop: c0-major (k32 column chunk), tap-minor. A loaded once per c0 as a
// contiguous site-id halo range; taps resolved via per-lane ldmatrix addresses.
// ===========================================================================
template<int CIN, bool LAST>
__global__ __launch_bounds__(256, 1)
void spconv_h(const __half* __restrict__ X, const int* __restrict__ nbr,
              const __half* __restrict__ Wp,
              const float* __restrict__ gamma, const float* __restrict__ beta,
              void* __restrict__ Yv)
{
    constexpr int NC0   = CIN / 32;
    constexpr int NITER = NC0 * KTAPS;

    extern __shared__ char smc[];
    const uint32_t smbase = smem_u32(smc);
    uint32_t* aslot = (uint32_t*)(smc + ASL_OFF);
    float*    sgam  = (float*)(smc + SG_OFF);
    float*    sbet  = (float*)(smc + SB_OFF);

    const int tid = threadIdx.x;
    const int m0  = blockIdx.x * 256;
    const int n0  = blockIdx.y * 128;
    const int base = (m0 > 136) ? (m0 - 136) : 0;

    // gamma/beta, zero rows, aslot LUT (all neighbors lie in [m0-129, m0+384])
    for (int i = tid; i < 128; i += 256) {
        sgam[i] = gamma[n0 + i];
        sbet[i] = beta[n0 + i];
    }
    if (tid < 20) {
        ((uint32_t*)(smc + ZSLOT * A_ROW_B))[tid] = 0;
        ((uint32_t*)(smc + A_BUF_B + ZSLOT * A_ROW_B))[tid] = 0;
    }
    #pragma unroll
    for (int t = 0; t < 9; t++) {                   // 2304 entries, 9 per thread
        const int i = t * 256 + tid;
        const int site = i / KTAPS, tap = i - site * KTAPS;
        const int nid = nbr[(size_t)m0 * KTAPS + i];
        const int slot = (nid < 0) ? ZSLOT : (nid - base);
        aslot[tap * 256 + site] = (uint32_t)(slot * A_ROW_B);
    }

    const int warp = tid >> 5, lane = tid & 31;
    const int wm  = (warp >> 1) * 64;
    const int wn  = (warp & 1) * 64;
    const int gid = lane >> 2;
    const int q   = lane & 3;
    const uint32_t a_lane = (uint32_t)((lane >> 4) * 16);
    const uint32_t b_off  = (uint32_t)(((lane & 7) + ((lane >> 4) & 1) * 8) * A_ROW_B
                                       + ((lane >> 3) & 1) * 16);

    float d[4][8][4];
    #pragma unroll
    for (int i = 0; i < 4; i++)
        #pragma unroll
        for (int j = 0; j < 8; j++)
            #pragma unroll
            for (int r = 0; r < 4; r++) d[i][j][r] = 0.f;

    // ---- contiguous halo load of one k32 column chunk into A buffer c0&1 ----
    auto loadA = [&](int c0) {
        const uint32_t ab = smbase + (uint32_t)(c0 & 1) * A_BUF_B;
        #pragma unroll
        for (int t = 0; t < 9; t++) {               // 528*4 = 2112 ops (last partial)
            const int g = t * 256 + tid;
            if (g < 528 * 4) {
                const int row = g >> 2, seg = g & 3;
                const long gr = (long)base + row;
                const bool ok = gr < NSITES;
                const __half* src = ok ? (X + gr * CIN + c0 * 32 + seg * 8) : X;
                cp16(ab + (uint32_t)(row * A_ROW_B + seg * 16), src, ok ? 16 : 0);
            }
        }
    };
    // ---- B chunk (cpos = iteration index) into stage it%3 ----
    auto loadB = [&](int it) {
        const uint32_t bb = smbase + B_OFF + (uint32_t)(it % 3) * B_STAGE_B;
        const __half* wc = Wp + (size_t)it * 16384;
        #pragma unroll
        for (int t = 0; t < 2; t++) {
            const int g = t * 256 + tid;
            const int nl = g >> 2, seg = g & 3;
            cp16(bb + (uint32_t)(nl * A_ROW_B + seg * 16),
                 wc + (size_t)(n0 + nl) * 32 + seg * 8, 16);
        }
    };

    // prologue: G0=A(0), G1=B(0), G2=B(1)
    loadA(0); CP_COMMIT();
    loadB(0); CP_COMMIT();
    loadB(1); CP_COMMIT();

    #pragma unroll 1
    for (int it = 0; it < NITER; it++) {
        const int c0 = it / KTAPS, tap = it - c0 * KTAPS;
        // exactly ONE commit group per iteration (keeps CP_WAIT(2) exact);
        // A(c0+1) rides in iteration (c0,1)'s group — safe: all warps passed
        // the (c0,0) barrier, so nobody still reads buffer (c0+1)&1.
        if (it + 2 < NITER) loadB(it + 2);
        if (tap == 1 && c0 + 1 < NC0) loadA(c0 + 1);
        CP_COMMIT();
        CP_WAIT(2);
        __syncthreads();

        // ---- MMA for (c0, tap): A via LUT slots, B stage it%3 ----
        const uint32_t ab = smbase + (uint32_t)(c0 & 1) * A_BUF_B;
        const uint32_t bb = smbase + B_OFF + (uint32_t)(it % 3) * B_STAGE_B;
        uint32_t asl[4];
        #pragma unroll
        for (int mt = 0; mt < 4; mt++)
            asl[mt] = aslot[tap * 256 + wm + mt * 16 + (lane & 15)];
        #pragma unroll
        for (int s16 = 0; s16 < 2; s16++) {
            uint32_t a[4][4];
            #pragma unroll
            for (int mt = 0; mt < 4; mt++)
                ldmx4(a[mt], ab + asl[mt] + (uint32_t)(s16 * 32) + a_lane);
            uint32_t b[8][2];
            #pragma unroll
            for (int np = 0; np < 4; np++) {
                uint32_t r[4];
                ldmx4(r, bb + (uint32_t)((wn + np * 16) * A_ROW_B + s16 * 32) + b_off);
                b[2 * np][0] = r[0];     b[2 * np][1] = r[1];
                b[2 * np + 1][0] = r[2]; b[2 * np + 1][1] = r[3];
            }
            #pragma unroll
            for (int nt = 0; nt < 8; nt++)
                #pragma unroll
                for (int mt = 0; mt < 4; mt++)
                    mma16(d[mt][nt], a[mt], b[nt]);
        }
    }

    // ---- fused GroupNorm(16-ch groups) + ReLU epilogue ----
    float* Yf = (float*)Yv;
    __half* Yh = (__half*)Yv;
    #pragma unroll
    for (int mt = 0; mt < 4; mt++) {
        #pragma unroll
        for (int h = 0; h < 2; h++) {
            const int row = m0 + wm + mt * 16 + gid + h * 8;
            const size_t rb = (size_t)row * HID + n0 + wn;
            #pragma unroll
            for (int g = 0; g < 4; g++) {
                const float v0 = d[mt][2 * g    ][2 * h];
                const float v1 = d[mt][2 * g    ][2 * h + 1];
                const float v2 = d[mt][2 * g + 1][2 * h];
                const float v3 = d[mt][2 * g + 1][2 * h + 1];
                float s  = v0 + v1 + v2 + v3;
                float ss = v0 * v0 + v1 * v1 + v2 * v2 + v3 * v3;
                s  += __shfl_xor_sync(0xffffffffu, s, 1);
                ss += __shfl_xor_sync(0xffffffffu, ss, 1);
                s  += __shfl_xor_sync(0xffffffffu, s, 2);
                ss += __shfl_xor_sync(0xffffffffu, ss, 2);
                const float mu  = s * (1.f / 16.f);
                const float var = ss * (1.f / 16.f) - mu * mu;
                const float rs  = rsqrtf(var + EPS);
                const int cb = wn + 16 * g + 2 * q;
                const float o0 = fmaxf(fmaf((v0 - mu) * rs, sgam[cb],     sbet[cb]),     0.f);
                const float o1 = fmaxf(fmaf((v1 - mu) * rs, sgam[cb + 1], sbet[cb + 1]), 0.f);
                const float o2 = fmaxf(fmaf((v2 - mu) * rs, sgam[cb + 8], sbet[cb + 8]), 0.f);
                const float o3 = fmaxf(fmaf((v3 - mu) * rs, sgam[cb + 9], sbet[cb + 9]), 0.f);
                if (LAST) {
                    *(float2*)(Yf + rb + 16 * g + 2 * q)     = make_float2(o0, o1);
                    *(float2*)(Yf + rb + 16 * g + 8 + 2 * q) = make_float2(o2, o3);
                } else {
                    *(__half2*)(Yh + rb + 16 * g + 2 * q)     = __floats2half2_rn(o0, o1);
                    *(__half2*)(Yh + rb + 16 * g + 8 + 2 * q) = __floats2half2_rn(o2, o3);
                }
            }
        }
    }
}

// ---------------------------------------------------------------------------
// Prep: transpose W [R,512] fp32 -> Wp [(c0*9+tap)][512][32] fp16 (RN).
// Source k-chunk by = tap*CPT + c0  ->  dest cpos = c0*9 + tap.
// ---------------------------------------------------------------------------
__global__ void w_prep(const float* __restrict__ W, __half* __restrict__ Wp, int CPT)
{
    __shared__ float t[32][33];
    const int bx = blockIdx.x;      // n tile
    const int by = blockIdx.y;      // source k chunk
    const int x = threadIdx.x, y = threadIdx.y;
    #pragma unroll
    for (int i = 0; i < 32; i += 8)
        t[y + i][x] = W[(size_t)(by * 32 + y + i) * 512 + bx * 32 + x];
    __syncthreads();
    const int tap = by / CPT, c0 = by - tap * CPT;
    const int cpos = c0 * KTAPS + tap;
    #pragma unroll
    for (int i = 0; i < 32; i += 8) {
        const int nl = y + i, kk = x;
        Wp[(size_t)cpos * 16384 + (size_t)(bx * 32 + nl) * 32 + kk] =
            __float2half_rn(t[kk][nl]);
    }
}

// Features fp32 -> fp16 (8 elems/thread)
__global__ void f2h(const float* __restrict__ src, __half* __restrict__ dst)
{
    const int t = blockIdx.x * blockDim.x + threadIdx.x;
    const float4* s = (const float4*)src + 2 * (size_t)t;
    const float4 v0 = s[0], v1 = s[1];
    __half2* o = (__half2*)dst + 4 * (size_t)t;
    o[0] = __floats2half2_rn(v0.x, v0.y);
    o[1] = __floats2half2_rn(v0.z, v0.w);
    o[2] = __floats2half2_rn(v1.x, v1.y);
    o[3] = __floats2half2_rn(v1.z, v1.w);
}

// ===========================================================================
// kernel_launch
// ===========================================================================
extern "C" void kernel_launch(void* const* d_in, const int* in_sizes, int n_in,
                              void* d_out, int out_size)
{
    const float* feat  = (const float*)d_in[0];
    const int*   nbr   = (const int*)  d_in[1];
    const float* w0    = (const float*)d_in[2];
    const float* wrest = (const float*)d_in[3];
    const float* gamma = (const float*)d_in[4];
    const float* beta  = (const float*)d_in[5];

    __half *actA, *actB, *featH, *Wp;
    cudaGetSymbolAddress((void**)&actA, g_actA);
    cudaGetSymbolAddress((void**)&actB, g_actB);
    cudaGetSymbolAddress((void**)&featH, g_featH);
    cudaGetSymbolAddress((void**)&Wp, g_Wp);

    cudaFuncSetAttribute(spconv_h<256, false>,
                         cudaFuncAttributeMaxDynamicSharedMemorySize, SMEM_BYTES);
    cudaFuncSetAttribute(spconv_h<512, false>,
                         cudaFuncAttributeMaxDynamicSharedMemorySize, SMEM_BYTES);
    cudaFuncSetAttribute(spconv_h<512, true>,
                         cudaFuncAttributeMaxDynamicSharedMemorySize, SMEM_BYTES);

    f2h<<<(NSITES * 256 / 8) / 256, 256>>>(feat, featH);
    w_prep<<<dim3(16, 72), dim3(32, 8)>>>(w0, Wp, 8);
    for (int l = 0; l < 7; l++)
        w_prep<<<dim3(16, 144), dim3(32, 8)>>>(
            wrest + (size_t)l * 4608 * 512, Wp + W0H + (size_t)l * WLH, 16);

    const dim3 grid(NSITES / 256, HID / 128);     // 512 x 4

    spconv_h<256, false><<<grid, 256, SMEM_BYTES>>>(featH, nbr, Wp, gamma, beta, actA);

    const __half* x = actA;
    __half*       y = actB;
    for (int l = 1; l < 8; l++) {
        const __half* wl = Wp + W0H + (size_t)(l - 1) * WLH;
        if (l == 7)
            spconv_h<512, true><<<grid, 256, SMEM_BYTES>>>(
                x, nbr, wl, gamma + l * HID, beta + l * HID, d_out);
        else
            spconv_h<512, false><<<grid, 256, SMEM_BYTES>>>(
                x, nbr, wl, gamma + l * HID, beta + l * HID, y);
        x = y;
        y = (y == actB) ? actA : actB;
    }
}

// round 10
// speedup vs baseline: 2.5687x; 1.2140x over previous
#include <cuda_runtime.h>
#include <cuda_fp16.h>
#include <cstdint>
#include <cstddef>

#define NSITES 131072
#define HID    512
#define KTAPS  9
#define EPS    1e-5f

// ---------------------------------------------------------------------------
// Device-global scratch (allocation-free rule)
// ---------------------------------------------------------------------------
__device__ __align__(16) __half g_actA[(size_t)NSITES * HID];
__device__ __align__(16) __half g_actB[(size_t)NSITES * HID];
__device__ __align__(16) __half g_featH[(size_t)NSITES * 256];
// Wp per layer: [cpos = c0*9+tap][n(512)][k(32)] fp16
#define W0H ((size_t)72  * 16384)
#define WLH ((size_t)144 * 16384)
__device__ __align__(16) __half g_Wp[W0H + 7 * WLH];

// ---------------------------------------------------------------------------
// Helpers (baseline PTX only — must pass ptxas at .target sm_103)
// ---------------------------------------------------------------------------
__device__ __forceinline__ uint32_t smem_u32(const void* p) {
    uint32_t a;
    asm("{ .reg .u64 t; cvta.to.shared.u64 t, %1; cvt.u32.u64 %0, t; }" : "=r"(a) : "l"(p));
    return a;
}
__device__ __forceinline__ void cp16(uint32_t dst, const void* src, int nbytes) {
    asm volatile("cp.async.cg.shared.global [%0], [%1], 16, %2;"
                 :: "r"(dst), "l"(src), "r"(nbytes));
}
__device__ __forceinline__ void mbar_init(uint32_t mbar, uint32_t cnt) {
    asm volatile("mbarrier.init.shared.b64 [%0], %1;" :: "r"(mbar), "r"(cnt) : "memory");
}
// arrive when ALL prior cp.async of this thread complete (counts as 1 arrival)
__device__ __forceinline__ void cp_arrive(uint32_t mbar) {
    asm volatile("cp.async.mbarrier.arrive.noinc.shared::cta.b64 [%0];"
                 :: "r"(mbar) : "memory");
}
__device__ __forceinline__ void mbar_arrive(uint32_t mbar) {
    asm volatile("mbarrier.arrive.shared.b64 _, [%0];" :: "r"(mbar) : "memory");
}
__device__ __forceinline__ void mbar_wait(uint32_t mbar, uint32_t parity) {
    asm volatile(
        "{\n\t.reg .pred P;\n\t"
        "LAB_%=:\n\t"
        "mbarrier.try_wait.parity.acquire.cta.shared::cta.b64 P, [%0], %1, 0x989680;\n\t"
        "@!P bra LAB_%=;\n\t}"
        :: "r"(mbar), "r"(parity) : "memory");
}
__device__ __forceinline__ void ldmx4(uint32_t* r, uint32_t addr) {
    asm volatile("ldmatrix.sync.aligned.m8n8.x4.shared.b16 {%0,%1,%2,%3}, [%4];"
                 : "=r"(r[0]), "=r"(r[1]), "=r"(r[2]), "=r"(r[3]) : "r"(addr));
}
__device__ __forceinline__ void mma16(float* d, const uint32_t* a, const uint32_t* b) {
    asm volatile(
        "mma.sync.aligned.m16n8k16.row.col.f32.f16.f16.f32 "
        "{%0,%1,%2,%3}, {%4,%5,%6,%7}, {%8,%9}, {%0,%1,%2,%3};"
        : "+f"(d[0]), "+f"(d[1]), "+f"(d[2]), "+f"(d[3])
        : "r"(a[0]), "r"(a[1]), "r"(a[2]), "r"(a[3]), "r"(b[0]), "r"(b[1]));
}

// ---------------------------------------------------------------------------
// SMEM layout (bytes).
//   A halo: 528 data rows + zero row, 80B stride, double-buffered.
//   B ring: 8 stages x 128 n-rows x 80B.
//   aslot LUT, gamma/beta, mbarriers.
// ---------------------------------------------------------------------------
#define A_ROW_B   80
#define ZSLOT     528
#define A_ROWS    530
#define A_BUF_B   (A_ROWS * A_ROW_B)        // 42400
#define B_OFF     (2 * A_BUF_B)             // 84800
#define B_STAGE_B (128 * A_ROW_B)           // 10240
#define NBSTG     8
#define ASL_OFF   (B_OFF + NBSTG * B_STAGE_B)   // 166720
#define SG_OFF    (ASL_OFF + 9216)          // 175936
#define SB_OFF    (SG_OFF + 512)            // 176448
#define MB_OFF    (SB_OFF + 512)            // 176960
#define SMEM_BYTES (MB_OFF + 160)           // 177120
// mbarrier slots (8B each): full_b[8], empty_b[8], full_a[2], empty_a[2]
#define FB(s) (mb + (uint32_t)((s) * 8))
#define EB(s) (mb + 64u + (uint32_t)((s) * 8))
#define FA(b) (mb + 128u + (uint32_t)((b) * 8))
#define EA(b) (mb + 144u + (uint32_t)((b) * 8))

// ===========================================================================
// Fused gather-GEMM (mma.sync fp16, fp32 acc) + GroupNorm + ReLU.
// CTA: 256 sites x 128 out-ch, 8 warps (warp tile 64x64).
// c0-major / tap-minor K loop; contiguous A halo; mbarrier rings — warps run
// desynchronized (NO __syncthreads in the mainloop).
// ===========================================================================
template<int CIN, bool LAST>
__global__ __launch_bounds__(256, 1)
void spconv_h(const __half* __restrict__ X, const int* __restrict__ nbr,
              const __half* __restrict__ Wp,
              const float* __restrict__ gamma, const float* __restrict__ beta,
              void* __restrict__ Yv)
{
    constexpr int NC0   = CIN / 32;
    constexpr int NITER = NC0 * KTAPS;

    extern __shared__ char smc[];
    const uint32_t smbase = smem_u32(smc);
    const uint32_t mb = smbase + MB_OFF;
    uint32_t* aslot = (uint32_t*)(smc + ASL_OFF);
    float*    sgam  = (float*)(smc + SG_OFF);
    float*    sbet  = (float*)(smc + SB_OFF);

    const int tid = threadIdx.x;
    const int m0  = blockIdx.x * 256;
    const int n0  = blockIdx.y * 128;
    const int base = (m0 > 136) ? (m0 - 136) : 0;

    for (int i = tid; i < 128; i += 256) {
        sgam[i] = gamma[n0 + i];
        sbet[i] = beta[n0 + i];
    }
    if (tid < 20) {
        ((uint32_t*)(smc + ZSLOT * A_ROW_B))[tid] = 0;
        ((uint32_t*)(smc + A_BUF_B + ZSLOT * A_ROW_B))[tid] = 0;
    }
    #pragma unroll
    for (int t = 0; t < 9; t++) {                   // 2304 LUT entries
        const int i = t * 256 + tid;
        const int site = i / KTAPS, tap = i - site * KTAPS;
        const int nid = nbr[(size_t)m0 * KTAPS + i];
        const int slot = (nid < 0) ? ZSLOT : (nid - base);
        aslot[tap * 256 + site] = (uint32_t)(slot * A_ROW_B);
    }
    if (tid < NBSTG) { mbar_init(FB(tid), 256); mbar_init(EB(tid), 256); }
    if (tid < 2)     { mbar_init(FA(tid), 256); mbar_init(EA(tid), 256); }
    __syncthreads();                                // the ONLY block barrier

    const int warp = tid >> 5, lane = tid & 31;
    const int wm  = (warp >> 1) * 64;
    const int wn  = (warp & 1) * 64;
    const int gid = lane >> 2;
    const int q   = lane & 3;
    const uint32_t a_lane = (uint32_t)((lane >> 4) * 16);
    const uint32_t b_off  = (uint32_t)(((lane & 7) + ((lane >> 4) & 1) * 8) * A_ROW_B
                                       + ((lane >> 3) & 1) * 16);

    float d[4][8][4];
    #pragma unroll
    for (int i = 0; i < 4; i++)
        #pragma unroll
        for (int j = 0; j < 8; j++)
            #pragma unroll
            for (int r = 0; r < 4; r++) d[i][j][r] = 0.f;

    // ---- contiguous halo load of one k32 column chunk into A buffer c0&1 ----
    auto loadA = [&](int c0) {
        const uint32_t ab = smbase + (uint32_t)(c0 & 1) * A_BUF_B;
        #pragma unroll
        for (int t = 0; t < 9; t++) {               // 2112 granules
            const int g = t * 256 + tid;
            if (g < 528 * 4) {
                const int row = g >> 2, seg = g & 3;
                const long gr = (long)base + row;
                const bool ok = gr < NSITES;
                const __half* src = ok ? (X + gr * CIN + c0 * 32 + seg * 8) : X;
                cp16(ab + (uint32_t)(row * A_ROW_B + seg * 16), src, ok ? 16 : 0);
            }
        }
    };
    // ---- B chunk cpos=pr into ring stage pr&7 ----
    auto loadB = [&](int pr) {
        const uint32_t bb = smbase + B_OFF + (uint32_t)(pr & 7) * B_STAGE_B;
        const __half* wc = Wp + (size_t)pr * 16384;
        #pragma unroll
        for (int t = 0; t < 2; t++) {
            const int g = t * 256 + tid;
            const int nl = g >> 2, seg = g & 3;
            cp16(bb + (uint32_t)(nl * A_ROW_B + seg * 16),
                 wc + (size_t)(n0 + nl) * 32 + seg * 8, 16);
        }
    };

    // prologue: A(0) + B stages 0..5
    loadA(0); cp_arrive(FA(0));
    #pragma unroll
    for (int pr = 0; pr < 6; pr++) { loadB(pr); cp_arrive(FB(pr)); }

    #pragma unroll 1
    for (int it = 0; it < NITER; it++) {
        const int c0 = it / KTAPS, tap = it - c0 * KTAPS;

        // --- B producer: stage pr&7, ring round pr>>3 ---
        const int pr = it + 6;
        if (pr < NITER) {
            const int s = pr & 7, r = pr >> 3;
            if (r >= 1) mbar_wait(EB(s), (uint32_t)((r - 1) & 1));
            loadB(pr);
            cp_arrive(FB(s));
        }
        // --- A producer: buffer (c0+1)&1, ring round (c0+1)>>1 ---
        if (tap == 1 && c0 + 1 < NC0) {
            const int ca = c0 + 1, rb = ca >> 1;
            if (rb >= 1) mbar_wait(EA(ca & 1), (uint32_t)((rb - 1) & 1));
            loadA(ca);
            cp_arrive(FA(ca & 1));
        }

        // --- consumers ---
        if (tap == 0) mbar_wait(FA(c0 & 1), (uint32_t)((c0 >> 1) & 1));
        mbar_wait(FB(it & 7), (uint32_t)((it >> 3) & 1));

        const uint32_t ab = smbase + (uint32_t)(c0 & 1) * A_BUF_B;
        const uint32_t bb = smbase + B_OFF + (uint32_t)(it & 7) * B_STAGE_B;
        uint32_t asl[4];
        #pragma unroll
        for (int mt = 0; mt < 4; mt++)
            asl[mt] = aslot[tap * 256 + wm + mt * 16 + (lane & 15)];
        #pragma unroll
        for (int s16 = 0; s16 < 2; s16++) {
            uint32_t a[4][4];
            #pragma unroll
            for (int mt = 0; mt < 4; mt++)
                ldmx4(a[mt], ab + asl[mt] + (uint32_t)(s16 * 32) + a_lane);
            uint32_t b[8][2];
            #pragma unroll
            for (int np = 0; np < 4; np++) {
                uint32_t r[4];
                ldmx4(r, bb + (uint32_t)((wn + np * 16) * A_ROW_B + s16 * 32) + b_off);
                b[2 * np][0] = r[0];     b[2 * np][1] = r[1];
                b[2 * np + 1][0] = r[2]; b[2 * np + 1][1] = r[3];
            }
            #pragma unroll
            for (int nt = 0; nt < 8; nt++)
                #pragma unroll
                for (int mt = 0; mt < 4; mt++)
                    mma16(d[mt][nt], a[mt], b[nt]);
        }

        mbar_arrive(EB(it & 7));
        if (tap == KTAPS - 1) mbar_arrive(EA(c0 & 1));
    }

    // ---- fused GroupNorm(16-ch groups) + ReLU epilogue ----
    float* Yf = (float*)Yv;
    __half* Yh = (__half*)Yv;
    #pragma unroll
    for (int mt = 0; mt < 4; mt++) {
        #pragma unroll
        for (int h = 0; h < 2; h++) {
            const int row = m0 + wm + mt * 16 + gid + h * 8;
            const size_t rb = (size_t)row * HID + n0 + wn;
            #pragma unroll
            for (int g = 0; g < 4; g++) {
                const float v0 = d[mt][2 * g    ][2 * h];
                const float v1 = d[mt][2 * g    ][2 * h + 1];
                const float v2 = d[mt][2 * g + 1][2 * h];
                const float v3 = d[mt][2 * g + 1][2 * h + 1];
                float s  = v0 + v1 + v2 + v3;
                float ss = v0 * v0 + v1 * v1 + v2 * v2 + v3 * v3;
                s  += __shfl_xor_sync(0xffffffffu, s, 1);
                ss += __shfl_xor_sync(0xffffffffu, ss, 1);
                s  += __shfl_xor_sync(0xffffffffu, s, 2);
                ss += __shfl_xor_sync(0xffffffffu, ss, 2);
                const float mu  = s * (1.f / 16.f);
                const float var = ss * (1.f / 16.f) - mu * mu;
                const float rs  = rsqrtf(var + EPS);
                const int cb = wn + 16 * g + 2 * q;
                const float o0 = fmaxf(fmaf((v0 - mu) * rs, sgam[cb],     sbet[cb]),     0.f);
                const float o1 = fmaxf(fmaf((v1 - mu) * rs, sgam[cb + 1], sbet[cb + 1]), 0.f);
                const float o2 = fmaxf(fmaf((v2 - mu) * rs, sgam[cb + 8], sbet[cb + 8]), 0.f);
                const float o3 = fmaxf(fmaf((v3 - mu) * rs, sgam[cb + 9], sbet[cb + 9]), 0.f);
                if (LAST) {
                    *(float2*)(Yf + rb + 16 * g + 2 * q)     = make_float2(o0, o1);
                    *(float2*)(Yf + rb + 16 * g + 8 + 2 * q) = make_float2(o2, o3);
                } else {
                    *(__half2*)(Yh + rb + 16 * g + 2 * q)     = __floats2half2_rn(o0, o1);
                    *(__half2*)(Yh + rb + 16 * g + 8 + 2 * q) = __floats2half2_rn(o2, o3);
                }
            }
        }
    }
}

// ---------------------------------------------------------------------------
// Prep: transpose W [R,512] fp32 -> Wp [(c0*9+tap)][512][32] fp16 (RN).
// ---------------------------------------------------------------------------
__global__ void w_prep(const float* __restrict__ W, __half* __restrict__ Wp, int CPT)
{
    __shared__ float t[32][33];
    const int bx = blockIdx.x;
    const int by = blockIdx.y;
    const int x = threadIdx.x, y = threadIdx.y;
    #pragma unroll
    for (int i = 0; i < 32; i += 8)
        t[y + i][x] = W[(size_t)(by * 32 + y + i) * 512 + bx * 32 + x];
    __syncthreads();
    const int tap = by / CPT, c0 = by - tap * CPT;
    const int cpos = c0 * KTAPS + tap;
    #pragma unroll
    for (int i = 0; i < 32; i += 8) {
        const int nl = y + i, kk = x;
        Wp[(size_t)cpos * 16384 + (size_t)(bx * 32 + nl) * 32 + kk] =
            __float2half_rn(t[kk][nl]);
    }
}

// Features fp32 -> fp16 (8 elems/thread)
__global__ void f2h(const float* __restrict__ src, __half* __restrict__ dst)
{
    const int t = blockIdx.x * blockDim.x + threadIdx.x;
    const float4* s = (const float4*)src + 2 * (size_t)t;
    const float4 v0 = s[0], v1 = s[1];
    __half2* o = (__half2*)dst + 4 * (size_t)t;
    o[0] = __floats2half2_rn(v0.x, v0.y);
    o[1] = __floats2half2_rn(v0.z, v0.w);
    o[2] = __floats2half2_rn(v1.x, v1.y);
    o[3] = __floats2half2_rn(v1.z, v1.w);
}

// ===========================================================================
// kernel_launch
// ===========================================================================
extern "C" void kernel_launch(void* const* d_in, const int* in_sizes, int n_in,
                              void* d_out, int out_size)
{
    const float* feat  = (const float*)d_in[0];
    const int*   nbr   = (const int*)  d_in[1];
    const float* w0    = (const float*)d_in[2];
    const float* wrest = (const float*)d_in[3];
    const float* gamma = (const float*)d_in[4];
    const float* beta  = (const float*)d_in[5];

    __half *actA, *actB, *featH, *Wp;
    cudaGetSymbolAddress((void**)&actA, g_actA);
    cudaGetSymbolAddress((void**)&actB, g_actB);
    cudaGetSymbolAddress((void**)&featH, g_featH);
    cudaGetSymbolAddress((void**)&Wp, g_Wp);

    cudaFuncSetAttribute(spconv_h<256, false>,
                         cudaFuncAttributeMaxDynamicSharedMemorySize, SMEM_BYTES);
    cudaFuncSetAttribute(spconv_h<512, false>,
                         cudaFuncAttributeMaxDynamicSharedMemorySize, SMEM_BYTES);
    cudaFuncSetAttribute(spconv_h<512, true>,
                         cudaFuncAttributeMaxDynamicSharedMemorySize, SMEM_BYTES);

    f2h<<<(NSITES * 256 / 8) / 256, 256>>>(feat, featH);
    w_prep<<<dim3(16, 72), dim3(32, 8)>>>(w0, Wp, 8);
    for (int l = 0; l < 7; l++)
        w_prep<<<dim3(16, 144), dim3(32, 8)>>>(
            wrest + (size_t)l * 4608 * 512, Wp + W0H + (size_t)l * WLH, 16);

    const dim3 grid(NSITES / 256, HID / 128);     // 512 x 4

    spconv_h<256, false><<<grid, 256, SMEM_BYTES>>>(featH, nbr, Wp, gamma, beta, actA);

    const __half* x = actA;
    __half*       y = actB;
    for (int l = 1; l < 8; l++) {
        const __half* wl = Wp + W0H + (size_t)(l - 1) * WLH;
        if (l == 7)
            spconv_h<512, true><<<grid, 256, SMEM_BYTES>>>(
                x, nbr, wl, gamma + l * HID, beta + l * HID, d_out);
        else
            spconv_h<512, false><<<grid, 256, SMEM_BYTES>>>(
                x, nbr, wl, gamma + l * HID, beta + l * HID, y);
        x = y;
        y = (y == actB) ? actA : actB;
    }
}

// round 11
// speedup vs baseline: 2.7786x; 1.0817x over previous
#include <cuda_runtime.h>
#include <cuda_fp16.h>
#include <cstdint>
#include <cstddef>

#define NSITES 131072
#define HID    512
#define KTAPS  9
#define EPS    1e-5f
#define NUNITS 4096                      // 8 layers x 512 m-blocks

// ---------------------------------------------------------------------------
// Device-global scratch (allocation-free rule)
// ---------------------------------------------------------------------------
__device__ __align__(16) __half g_actA[(size_t)NSITES * HID];
__device__ __align__(16) __half g_actB[(size_t)NSITES * HID];
__device__ __align__(16) __half g_featH[(size_t)NSITES * 256];
#define W0H ((size_t)72  * 16384)
#define WLH ((size_t)144 * 16384)
__device__ __align__(16) __half g_Wp[W0H + 7 * WLH];
__device__ int g_flags[NUNITS];          // 1 = unit complete (all 4 n-blocks)

// ---------------------------------------------------------------------------
// Helpers (baseline PTX only — must pass ptxas at .target sm_103)
// ---------------------------------------------------------------------------
__device__ __forceinline__ uint32_t smem_u32(const void* p) {
    uint32_t a;
    asm("{ .reg .u64 t; cvta.to.shared.u64 t, %1; cvt.u32.u64 %0, t; }" : "=r"(a) : "l"(p));
    return a;
}
__device__ __forceinline__ void cp16(uint32_t dst, const void* src, int nbytes) {
    asm volatile("cp.async.cg.shared.global [%0], [%1], 16, %2;"
                 :: "r"(dst), "l"(src), "r"(nbytes));
}
__device__ __forceinline__ void mbar_init(uint32_t mbar, uint32_t cnt) {
    asm volatile("mbarrier.init.shared.b64 [%0], %1;" :: "r"(mbar), "r"(cnt) : "memory");
}
__device__ __forceinline__ void cp_arrive(uint32_t mbar) {
    asm volatile("cp.async.mbarrier.arrive.noinc.shared::cta.b64 [%0];"
                 :: "r"(mbar) : "memory");
}
__device__ __forceinline__ void mbar_arrive(uint32_t mbar) {
    asm volatile("mbarrier.arrive.shared.b64 _, [%0];" :: "r"(mbar) : "memory");
}
__device__ __forceinline__ void mbar_wait(uint32_t mbar, uint32_t parity) {
    asm volatile(
        "{\n\t.reg .pred P;\n\t"
        "LAB_%=:\n\t"
        "mbarrier.try_wait.parity.acquire.cta.shared::cta.b64 P, [%0], %1, 0x989680;\n\t"
        "@!P bra LAB_%=;\n\t}"
        :: "r"(mbar), "r"(parity) : "memory");
}
__device__ __forceinline__ int ld_acq(const int* p) {
    int v;
    asm volatile("ld.acquire.gpu.global.b32 %0, [%1];" : "=r"(v) : "l"(p) : "memory");
    return v;
}
__device__ __forceinline__ void st_rel(int* p, int v) {
    asm volatile("st.release.gpu.global.b32 [%0], %1;" :: "l"(p), "r"(v) : "memory");
}
__device__ __forceinline__ void ldmx4(uint32_t* r, uint32_t addr) {
    asm volatile("ldmatrix.sync.aligned.m8n8.x4.shared.b16 {%0,%1,%2,%3}, [%4];"
                 : "=r"(r[0]), "=r"(r[1]), "=r"(r[2]), "=r"(r[3]) : "r"(addr));
}
__device__ __forceinline__ void mma16(float* d, const uint32_t* a, const uint32_t* b) {
    asm volatile(
        "mma.sync.aligned.m16n8k16.row.col.f32.f16.f16.f32 "
        "{%0,%1,%2,%3}, {%4,%5,%6,%7}, {%8,%9}, {%0,%1,%2,%3};"
        : "+f"(d[0]), "+f"(d[1]), "+f"(d[2]), "+f"(d[3])
        : "r"(a[0]), "r"(a[1]), "r"(a[2]), "r"(a[3]), "r"(b[0]), "r"(b[1]));
}

// ---------------------------------------------------------------------------
// SMEM layout (bytes)
// ---------------------------------------------------------------------------
#define A_ROW_B   80
#define ZSLOT     528
#define A_ROWS    530
#define A_BUF_B   (A_ROWS * A_ROW_B)        // 42400
#define B_OFF     (2 * A_BUF_B)             // 84800
#define B_STAGE_B (128 * A_ROW_B)           // 10240
#define ASL_OFF   (B_OFF + 8 * B_STAGE_B)   // 166720
#define SG_OFF    (ASL_OFF + 9216)          // 175936 (512 f32)
#define SB_OFF    (SG_OFF + 2048)           // 177984
#define MB_OFF    (SB_OFF + 2048)           // 180032
#define SMEM_BYTES (MB_OFF + 160)           // 180192
#define FB(s) (mb + (uint32_t)((s) * 8))
#define EB(s) (mb + 64u + (uint32_t)((s) * 8))
#define FA(b) (mb + 128u + (uint32_t)((b) * 8))
#define EA(b) (mb + 144u + (uint32_t)((b) * 8))

// ===========================================================================
// Persistent fused head: 148 CTAs, unit = (layer, m-block of 256 sites),
// each unit runs 4 n-blocks of 128 out-ch. Flag dataflow across layers.
// Ring mbarrier state carries across units via cumulative round counters.
// ===========================================================================
__global__ __launch_bounds__(256, 1)
void spconv_all(const __half* __restrict__ featH, const int* __restrict__ nbr,
                const __half* __restrict__ Wp,
                const float* __restrict__ gamma, const float* __restrict__ beta,
                __half* __restrict__ actA, __half* __restrict__ actB,
                float* __restrict__ outF)
{
    extern __shared__ char smc[];
    const uint32_t smbase = smem_u32(smc);
    const uint32_t mb = smbase + MB_OFF;
    uint32_t* aslot = (uint32_t*)(smc + ASL_OFF);
    float*    sgam  = (float*)(smc + SG_OFF);
    float*    sbet  = (float*)(smc + SB_OFF);

    const int tid = threadIdx.x;
    if (tid < 20) {
        ((uint32_t*)(smc + ZSLOT * A_ROW_B))[tid] = 0;
        ((uint32_t*)(smc + A_BUF_B + ZSLOT * A_ROW_B))[tid] = 0;
    }
    if (tid < 8) { mbar_init(FB(tid), 256); mbar_init(EB(tid), 256); }
    if (tid < 2) { mbar_init(FA(tid), 256); mbar_init(EA(tid), 256); }
    __syncthreads();

    const int warp = tid >> 5, lane = tid & 31;
    const int wm  = (warp >> 1) * 64;
    const int wn  = (warp & 1) * 64;
    const int gid = lane >> 2;
    const int q   = lane & 3;
    const uint32_t a_lane = (uint32_t)((lane >> 4) * 16);
    const uint32_t b_loff = (uint32_t)(((lane & 7) + ((lane >> 4) & 1) * 8) * A_ROW_B
                                       + ((lane >> 3) & 1) * 16);

    int rb = 0;     // cumulative B-ring rounds consumed/produced per stage
    int ra = 0;     // cumulative A-buffer rounds per buffer

    #pragma unroll 1
    for (int u = blockIdx.x; u < NUNITS; u += gridDim.x) {
        const int l = u >> 9, m = u & 511;
        const int m0   = m << 8;
        const int base = (m0 > 136) ? (m0 - 136) : 0;
        const int CIN   = l ? 512 : 256;
        const int NC0   = CIN >> 5;
        const int NITER = NC0 * KTAPS;
        const __half* X  = (l == 0) ? featH : ((l & 1) ? actA : actB);
        const __half* Wl = (l == 0) ? Wp : (Wp + W0H + (size_t)(l - 1) * WLH);
        const bool LAST = (l == 7);
        __half* OH = (l & 1) ? actB : actA;

        // ---- per-unit setup: gamma/beta + LUT (prev unit ended in syncthreads) ----
        for (int i = tid; i < 512; i += 256) {
            sgam[i] = gamma[l * 512 + i];
            sbet[i] = beta[l * 512 + i];
        }
        #pragma unroll
        for (int t = 0; t < 9; t++) {
            const int i = t * 256 + tid;
            const int site = i / KTAPS, tap = i - site * KTAPS;
            const int nid = nbr[(size_t)m0 * KTAPS + i];
            const int slot = (nid < 0) ? ZSLOT : (nid - base);
            aslot[tap * 256 + site] = (uint32_t)(slot * A_ROW_B);
        }
        // ---- dependency wait: layer l-1 m-blocks {m-1,m,m+1} complete ----
        if (l > 0 && tid < 3) {
            const int mm = m - 1 + tid;
            if (mm >= 0 && mm < 512) {
                const int* fp = &g_flags[(l - 1) * 512 + mm];
                while (ld_acq(fp) == 0)
                    asm volatile("nanosleep.u32 128;");
            }
        }
        __syncthreads();    // LUT/params visible + deps satisfied for all threads

        #pragma unroll 1
        for (int nb = 0; nb < 4; nb++) {
            const int n0 = nb << 7;

            auto loadA = [&](int c0) {
                const uint32_t ab = smbase + (uint32_t)(c0 & 1) * A_BUF_B;
                #pragma unroll
                for (int t = 0; t < 9; t++) {
                    const int g = t * 256 + tid;
                    if (g < 528 * 4) {
                        const int row = g >> 2, seg = g & 3;
                        const long gr = (long)base + row;
                        const bool ok = gr < NSITES;
                        const __half* src = ok ? (X + gr * CIN + c0 * 32 + seg * 8) : X;
                        cp16(ab + (uint32_t)(row * A_ROW_B + seg * 16), src, ok ? 16 : 0);
                    }
                }
            };
            auto loadB = [&](int pr) {
                const uint32_t bb = smbase + B_OFF + (uint32_t)(pr & 7) * B_STAGE_B;
                const __half* wc = Wl + (size_t)pr * 16384;
                #pragma unroll
                for (int t = 0; t < 2; t++) {
                    const int g = t * 256 + tid;
                    const int nl = g >> 2, seg = g & 3;
                    cp16(bb + (uint32_t)(nl * A_ROW_B + seg * 16),
                         wc + (size_t)(n0 + nl) * 32 + seg * 8, 16);
                }
            };

            // prologue: B stages 0..5, A(0)
            #pragma unroll 1
            for (int pr = 0; pr < 6; pr++) {
                if (rb >= 1) mbar_wait(EB(pr), (uint32_t)((rb - 1) & 1));
                loadB(pr);
                cp_arrive(FB(pr));
            }
            if (ra >= 1) mbar_wait(EA(0), (uint32_t)((ra - 1) & 1));
            loadA(0);
            cp_arrive(FA(0));

            float d[4][8][4];
            #pragma unroll
            for (int i = 0; i < 4; i++)
                #pragma unroll
                for (int j = 0; j < 8; j++)
                    #pragma unroll
                    for (int r = 0; r < 4; r++) d[i][j][r] = 0.f;

            #pragma unroll 1
            for (int it = 0; it < NITER; it++) {
                const int c0 = it / KTAPS, tap = it - c0 * KTAPS;

                const int pr = it + 6;
                if (pr < NITER) {
                    const int r = rb + (pr >> 3);
                    if (r >= 1) mbar_wait(EB(pr & 7), (uint32_t)((r - 1) & 1));
                    loadB(pr);
                    cp_arrive(FB(pr & 7));
                }
                if (tap == 1 && c0 + 1 < NC0) {
                    const int ca = c0 + 1;
                    const int rr = ra + (ca >> 1);
                    if (rr >= 1) mbar_wait(EA(ca & 1), (uint32_t)((rr - 1) & 1));
                    loadA(ca);
                    cp_arrive(FA(ca & 1));
                }

                if (tap == 0) mbar_wait(FA(c0 & 1), (uint32_t)((ra + (c0 >> 1)) & 1));
                mbar_wait(FB(it & 7), (uint32_t)((rb + (it >> 3)) & 1));

                const uint32_t ab = smbase + (uint32_t)(c0 & 1) * A_BUF_B;
                const uint32_t bb = smbase + B_OFF + (uint32_t)(it & 7) * B_STAGE_B;
                uint32_t asl[4];
                #pragma unroll
                for (int mt = 0; mt < 4; mt++)
                    asl[mt] = aslot[tap * 256 + wm + mt * 16 + (lane & 15)];
                #pragma unroll
                for (int s16 = 0; s16 < 2; s16++) {
                    uint32_t a[4][4];
                    #pragma unroll
                    for (int mt = 0; mt < 4; mt++)
                        ldmx4(a[mt], ab + asl[mt] + (uint32_t)(s16 * 32) + a_lane);
                    uint32_t b[8][2];
                    #pragma unroll
                    for (int np = 0; np < 4; np++) {
                        uint32_t r[4];
                        ldmx4(r, bb + (uint32_t)((wn + np * 16) * A_ROW_B + s16 * 32)
                                 + b_loff);
                        b[2 * np][0] = r[0];     b[2 * np][1] = r[1];
                        b[2 * np + 1][0] = r[2]; b[2 * np + 1][1] = r[3];
                    }
                    #pragma unroll
                    for (int nt = 0; nt < 8; nt++)
                        #pragma unroll
                        for (int mt = 0; mt < 4; mt++)
                            mma16(d[mt][nt], a[mt], b[nt]);
                }

                mbar_arrive(EB(it & 7));
                if (tap == KTAPS - 1) mbar_arrive(EA(c0 & 1));
            }
            rb += NITER >> 3;   // 9 or 18 rounds per n-block
            ra += NC0 >> 1;     // 4 or 8

            // ---- fused GroupNorm(16-ch) + ReLU epilogue for this n-block ----
            #pragma unroll
            for (int mt = 0; mt < 4; mt++) {
                #pragma unroll
                for (int h = 0; h < 2; h++) {
                    const int row = m0 + wm + mt * 16 + gid + h * 8;
                    const size_t rbase = (size_t)row * HID + n0 + wn;
                    #pragma unroll
                    for (int g = 0; g < 4; g++) {
                        const float v0 = d[mt][2 * g    ][2 * h];
                        const float v1 = d[mt][2 * g    ][2 * h + 1];
                        const float v2 = d[mt][2 * g + 1][2 * h];
                        const float v3 = d[mt][2 * g + 1][2 * h + 1];
                        float s  = v0 + v1 + v2 + v3;
                        float ss = v0 * v0 + v1 * v1 + v2 * v2 + v3 * v3;
                        s  += __shfl_xor_sync(0xffffffffu, s, 1);
                        ss += __shfl_xor_sync(0xffffffffu, ss, 1);
                        s  += __shfl_xor_sync(0xffffffffu, s, 2);
                        ss += __shfl_xor_sync(0xffffffffu, ss, 2);
                        const float mu  = s * (1.f / 16.f);
                        const float var = ss * (1.f / 16.f) - mu * mu;
                        const float rs  = rsqrtf(var + EPS);
                        const int cb = n0 + wn + 16 * g + 2 * q;   // col in [0,512)
                        const float o0 = fmaxf(fmaf((v0 - mu) * rs, sgam[cb],     sbet[cb]),     0.f);
                        const float o1 = fmaxf(fmaf((v1 - mu) * rs, sgam[cb + 1], sbet[cb + 1]), 0.f);
                        const float o2 = fmaxf(fmaf((v2 - mu) * rs, sgam[cb + 8], sbet[cb + 8]), 0.f);
                        const float o3 = fmaxf(fmaf((v3 - mu) * rs, sgam[cb + 9], sbet[cb + 9]), 0.f);
                        if (LAST) {
                            *(float2*)(outF + rbase + 16 * g + 2 * q)     = make_float2(o0, o1);
                            *(float2*)(outF + rbase + 16 * g + 8 + 2 * q) = make_float2(o2, o3);
                        } else {
                            *(__half2*)(OH + rbase + 16 * g + 2 * q)     = __floats2half2_rn(o0, o1);
                            *(__half2*)(OH + rbase + 16 * g + 8 + 2 * q) = __floats2half2_rn(o2, o3);
                        }
                    }
                }
            }
        }

        // ---- unit complete: publish ----
        __threadfence();
        __syncthreads();
        if (tid == 0) st_rel(&g_flags[u], 1);
    }
}

// ---------------------------------------------------------------------------
// Prep kernels
// ---------------------------------------------------------------------------
__global__ void reset_flags() {
    int* f;
    f = g_flags;
    f[blockIdx.x * 256 + threadIdx.x] = 0;
}
__global__ void w_prep(const float* __restrict__ W, __half* __restrict__ Wp, int CPT)
{
    __shared__ float t[32][33];
    const int bx = blockIdx.x;
    const int by = blockIdx.y;
    const int x = threadIdx.x, y = threadIdx.y;
    #pragma unroll
    for (int i = 0; i < 32; i += 8)
        t[y + i][x] = W[(size_t)(by * 32 + y + i) * 512 + bx * 32 + x];
    __syncthreads();
    const int tap = by / CPT, c0 = by - tap * CPT;
    const int cpos = c0 * KTAPS + tap;
    #pragma unroll
    for (int i = 0; i < 32; i += 8) {
        const int nl = y + i, kk = x;
        Wp[(size_t)cpos * 16384 + (size_t)(bx * 32 + nl) * 32 + kk] =
            __float2half_rn(t[kk][nl]);
    }
}
__global__ void f2h(const float* __restrict__ src, __half* __restrict__ dst)
{
    const int t = blockIdx.x * blockDim.x + threadIdx.x;
    const float4* s = (const float4*)src + 2 * (size_t)t;
    const float4 v0 = s[0], v1 = s[1];
    __half2* o = (__half2*)dst + 4 * (size_t)t;
    o[0] = __floats2half2_rn(v0.x, v0.y);
    o[1] = __floats2half2_rn(v0.z, v0.w);
    o[2] = __floats2half2_rn(v1.x, v1.y);
    o[3] = __floats2half2_rn(v1.z, v1.w);
}

// ===========================================================================
// kernel_launch: prep + flag reset + one persistent fused kernel.
// ===========================================================================
extern "C" void kernel_launch(void* const* d_in, const int* in_sizes, int n_in,
                              void* d_out, int out_size)
{
    const float* feat  = (const float*)d_in[0];
    const int*   nbr   = (const int*)  d_in[1];
    const float* w0    = (const float*)d_in[2];
    const float* wrest = (const float*)d_in[3];
    const float* gamma = (const float*)d_in[4];
    const float* beta  = (const float*)d_in[5];

    __half *actA, *actB, *featH, *Wp;
    cudaGetSymbolAddress((void**)&actA, g_actA);
    cudaGetSymbolAddress((void**)&actB, g_actB);
    cudaGetSymbolAddress((void**)&featH, g_featH);
    cudaGetSymbolAddress((void**)&Wp, g_Wp);

    cudaFuncSetAttribute(spconv_all,
                         cudaFuncAttributeMaxDynamicSharedMemorySize, SMEM_BYTES);

    f2h<<<(NSITES * 256 / 8) / 256, 256>>>(feat, featH);
    w_prep<<<dim3(16, 72), dim3(32, 8)>>>(w0, Wp, 8);
    for (int l = 0; l < 7; l++)
        w_prep<<<dim3(16, 144), dim3(32, 8)>>>(
            wrest + (size_t)l * 4608 * 512, Wp + W0H + (size_t)l * WLH, 16);
    reset_flags<<<NUNITS / 256, 256>>>();

    spconv_all<<<148, 256, SMEM_BYTES>>>(featH, nbr, Wp, gamma, beta,
                                         actA, actB, (float*)d_out);
}

// round 12
// speedup vs baseline: 2.8872x; 1.0391x over previous
#include <cuda_runtime.h>
#include <cuda_fp16.h>
#include <cstdint>
#include <cstddef>

#define NSITES 131072
#define HID    512
#define KTAPS  9
#define EPS    1e-5f
#define NUNITS 4096                      // 8 layers x 512 m-blocks

// ---------------------------------------------------------------------------
// Device-global scratch (allocation-free rule)
// ---------------------------------------------------------------------------
__device__ __align__(16) __half g_actA[(size_t)NSITES * HID];
__device__ __align__(16) __half g_actB[(size_t)NSITES * HID];
__device__ __align__(16) __half g_featH[(size_t)NSITES * 256];
#define W0H ((size_t)72  * 16384)
#define WLH ((size_t)144 * 16384)
__device__ __align__(16) __half g_Wp[W0H + 7 * WLH];
__device__ int g_flags[NUNITS];
__device__ unsigned g_ticket;

// ---------------------------------------------------------------------------
// Helpers (baseline PTX only — must pass ptxas at .target sm_103)
// ---------------------------------------------------------------------------
__device__ __forceinline__ uint32_t smem_u32(const void* p) {
    uint32_t a;
    asm("{ .reg .u64 t; cvta.to.shared.u64 t, %1; cvt.u32.u64 %0, t; }" : "=r"(a) : "l"(p));
    return a;
}
__device__ __forceinline__ void cp16(uint32_t dst, const void* src, int nbytes) {
    asm volatile("cp.async.cg.shared.global [%0], [%1], 16, %2;"
                 :: "r"(dst), "l"(src), "r"(nbytes));
}
__device__ __forceinline__ void mbar_init(uint32_t mbar, uint32_t cnt) {
    asm volatile("mbarrier.init.shared.b64 [%0], %1;" :: "r"(mbar), "r"(cnt) : "memory");
}
__device__ __forceinline__ void cp_arrive(uint32_t mbar) {
    asm volatile("cp.async.mbarrier.arrive.noinc.shared::cta.b64 [%0];"
                 :: "r"(mbar) : "memory");
}
__device__ __forceinline__ void mbar_arrive(uint32_t mbar) {
    asm volatile("mbarrier.arrive.shared.b64 _, [%0];" :: "r"(mbar) : "memory");
}
__device__ __forceinline__ void mbar_wait(uint32_t mbar, uint32_t parity) {
    asm volatile(
        "{\n\t.reg .pred P;\n\t"
        "LAB_%=:\n\t"
        "mbarrier.try_wait.parity.acquire.cta.shared::cta.b64 P, [%0], %1, 0x989680;\n\t"
        "@!P bra LAB_%=;\n\t}"
        :: "r"(mbar), "r"(parity) : "memory");
}
__device__ __forceinline__ int ld_acq(const int* p) {
    int v;
    asm volatile("ld.acquire.gpu.global.b32 %0, [%1];" : "=r"(v) : "l"(p) : "memory");
    return v;
}
__device__ __forceinline__ void st_rel(int* p, int v) {
    asm volatile("st.release.gpu.global.b32 [%0], %1;" :: "l"(p), "r"(v) : "memory");
}
__device__ __forceinline__ void ldmx4(uint32_t* r, uint32_t addr) {
    asm volatile("ldmatrix.sync.aligned.m8n8.x4.shared.b16 {%0,%1,%2,%3}, [%4];"
                 : "=r"(r[0]), "=r"(r[1]), "=r"(r[2]), "=r"(r[3]) : "r"(addr));
}
__device__ __forceinline__ void mma16(float* d, const uint32_t* a, const uint32_t* b) {
    asm volatile(
        "mma.sync.aligned.m16n8k16.row.col.f32.f16.f16.f32 "
        "{%0,%1,%2,%3}, {%4,%5,%6,%7}, {%8,%9}, {%0,%1,%2,%3};"
        : "+f"(d[0]), "+f"(d[1]), "+f"(d[2]), "+f"(d[3])
        : "r"(a[0]), "r"(a[1]), "r"(a[2]), "r"(a[3]), "r"(b[0]), "r"(b[1]));
}

// ---------------------------------------------------------------------------
// SMEM layout (bytes)
// ---------------------------------------------------------------------------
#define A_ROW_B   80
#define ZSLOT     528
#define A_ROWS    530
#define A_BUF_B   (A_ROWS * A_ROW_B)        // 42400
#define B_OFF     (2 * A_BUF_B)             // 84800
#define B_STAGE_B (128 * A_ROW_B)           // 10240
#define ASL_OFF   (B_OFF + 8 * B_STAGE_B)   // 166720
#define SG_OFF    (ASL_OFF + 9216)          // 175936 (512 f32)
#define SB_OFF    (SG_OFF + 2048)           // 177984
#define MB_OFF    (SB_OFF + 2048)           // 180032
#define TK_OFF    (MB_OFF + 160)            // 180192 (ticket int)
#define SMEM_BYTES (TK_OFF + 16)            // 180208
#define FB(s) (mb + (uint32_t)((s) * 8))
#define EB(s) (mb + 64u + (uint32_t)((s) * 8))
#define FA(b) (mb + 128u + (uint32_t)((b) * 8))
#define EA(b) (mb + 144u + (uint32_t)((b) * 8))

// ===========================================================================
// Persistent fused head: 148 CTAs, atomic-ticket units = (layer, m-block).
// Continuous A/B producer streams (B prefetches across units); cumulative
// ring counters Ap/Ac/Bp/Bc; flag dataflow across layers.
// ===========================================================================
__global__ __launch_bounds__(256, 1)
void spconv_all(const __half* __restrict__ featH, const int* __restrict__ nbr,
                const __half* __restrict__ Wp,
                const float* __restrict__ gamma, const float* __restrict__ beta,
                __half* __restrict__ actA, __half* __restrict__ actB,
                float* __restrict__ outF)
{
    extern __shared__ char smc[];
    const uint32_t smbase = smem_u32(smc);
    const uint32_t mb = smbase + MB_OFF;
    uint32_t* aslot = (uint32_t*)(smc + ASL_OFF);
    float*    sgam  = (float*)(smc + SG_OFF);
    float*    sbet  = (float*)(smc + SB_OFF);
    int*      stkt  = (int*)(smc + TK_OFF);

    const int tid = threadIdx.x;
    if (tid < 20) {
        ((uint32_t*)(smc + ZSLOT * A_ROW_B))[tid] = 0;
        ((uint32_t*)(smc + A_BUF_B + ZSLOT * A_ROW_B))[tid] = 0;
    }
    if (tid < 8) { mbar_init(FB(tid), 256); mbar_init(EB(tid), 256); }
    if (tid < 2) { mbar_init(FA(tid), 256); mbar_init(EA(tid), 256); }
    if (tid == 0) *stkt = (int)atomicAdd(&g_ticket, 1u);
    __syncthreads();
    int u = *stkt;

    const int warp = tid >> 5, lane = tid & 31;
    const int wm  = (warp >> 1) * 64;
    const int wn  = (warp & 1) * 64;
    const int gid = lane >> 2;
    const int q   = lane & 3;
    const uint32_t a_lane = (uint32_t)((lane >> 4) * 16);
    const uint32_t b_loff = (uint32_t)(((lane & 7) + ((lane >> 4) & 1) * 8) * A_ROW_B
                                       + ((lane >> 3) & 1) * 16);

    int Ap = 0, Ac = 0, Bp = 0, Bc = 0;   // cumulative ring counters

    #pragma unroll 1
    while (u < NUNITS) {
        const int l = u >> 9, m = u & 511;
        const int m0   = m << 8;
        const int base = (m0 > 136) ? (m0 - 136) : 0;
        const int CIN   = l ? 512 : 256;
        const int NC0   = CIN >> 5;               // 8 or 16 (power of 2)
        const int NITER = NC0 * KTAPS;
        const __half* X  = (l == 0) ? featH : ((l & 1) ? actA : actB);
        const __half* Wl = (l == 0) ? Wp : (Wp + W0H + (size_t)(l - 1) * WLH);
        const bool LAST = (l == 7);
        __half* OH = (l & 1) ? actB : actA;

        if (tid == 0) *stkt = (int)atomicAdd(&g_ticket, 1u);
        for (int i = tid; i < 512; i += 256) {
            sgam[i] = gamma[l * 512 + i];
            sbet[i] = beta[l * 512 + i];
        }
        #pragma unroll
        for (int t = 0; t < 9; t++) {
            const int i = t * 256 + tid;
            const int site = i / KTAPS, tap = i - site * KTAPS;
            const int nid = nbr[(size_t)m0 * KTAPS + i];
            const int slot = (nid < 0) ? ZSLOT : (nid - base);
            aslot[tap * 256 + site] = (uint32_t)(slot * A_ROW_B);
        }
        if (l > 0 && tid < 3) {
            const int mm = m - 1 + tid;
            if (mm >= 0 && mm < 512) {
                const int* fp = &g_flags[(l - 1) * 512 + mm];
                while (ld_acq(fp) == 0)
                    asm volatile("nanosleep.u32 128;");
            }
        }
        __syncthreads();
        const int u_next = *stkt;
        const bool pf_next = (u_next < NUNITS);
        const __half* WlN = Wp;
        if (pf_next) {
            const int ln = u_next >> 9;
            WlN = (ln == 0) ? Wp : (Wp + W0H + (size_t)(ln - 1) * WLH);
        }

        auto loadA = [&](int c0, int buf) {
            const uint32_t ab = smbase + (uint32_t)buf * A_BUF_B;
            #pragma unroll
            for (int t = 0; t < 9; t++) {
                const int g = t * 256 + tid;
                if (g < 528 * 4) {
                    const int row = g >> 2, seg = g & 3;
                    const long gr = (long)base + row;
                    const bool ok = gr < NSITES;
                    const __half* src = ok ? (X + gr * CIN + c0 * 32 + seg * 8) : X;
                    cp16(ab + (uint32_t)(row * A_ROW_B + seg * 16), src, ok ? 16 : 0);
                }
            }
        };
        auto loadBr = [&](int s, const __half* wc, int n0p) {
            const uint32_t bb = smbase + B_OFF + (uint32_t)s * B_STAGE_B;
            #pragma unroll
            for (int t = 0; t < 2; t++) {
                const int g = t * 256 + tid;
                const int nl = g >> 2, seg = g & 3;
                cp16(bb + (uint32_t)(nl * A_ROW_B + seg * 16),
                     wc + (size_t)(n0p + nl) * 32 + seg * 8, 16);
            }
        };

        // ---- A prologue: chunk 0 of this unit ----
        {
            const int b = Ap & 1, r = Ap >> 1;
            if (r >= 1) mbar_wait(EA(b), (uint32_t)((r - 1) & 1));
            loadA(0, b);
            cp_arrive(FA(b));
            Ap++;
        }
        // ---- B prologue: first unit of this CTA only ----
        if (Bp == 0) {
            #pragma unroll 1
            for (int p = 0; p < 6; p++) {
                loadBr(p, Wl + (size_t)p * 16384, 0);
                cp_arrive(FB(p));
                Bp++;
            }
        }
        int pcp = 6, pnb = 0;        // B produce cursor (pnb==4 => next unit)
        const int Ac0 = Ac;

        #pragma unroll 1
        for (int nb = 0; nb < 4; nb++) {
            const int n0 = nb << 7;
            float d[4][8][4];
            #pragma unroll
            for (int i = 0; i < 4; i++)
                #pragma unroll
                for (int j = 0; j < 8; j++)
                    #pragma unroll
                    for (int r = 0; r < 4; r++) d[i][j][r] = 0.f;

            #pragma unroll 1
            for (int it = 0; it < NITER; it++) {
                const int c0 = it / KTAPS, tap = it - c0 * KTAPS;

                // --- B producer: exactly one chunk per iteration ---
                if (pnb < 4 || (pnb == 4 && pcp < 6 && pf_next)) {
                    const __half* wsrc = (pnb < 4) ? (Wl + (size_t)pcp * 16384)
                                                   : (WlN + (size_t)pcp * 16384);
                    const int n0p = (pnb < 4) ? (pnb << 7) : 0;
                    const int s = Bp & 7, r = Bp >> 3;
                    if (r >= 1) mbar_wait(EB(s), (uint32_t)((r - 1) & 1));
                    loadBr(s, wsrc, n0p);
                    cp_arrive(FB(s));
                    Bp++;
                    const int lim = (pnb < 4) ? NITER : 6;
                    if (++pcp == lim) { pcp = 0; pnb++; }
                }
                // --- A producer: next chunk in the flattened per-unit stream ---
                if (tap == 1) {
                    const int la = Ac - Ac0;          // chunk currently consumed
                    if (la + 1 < 4 * NC0) {
                        const int b = Ap & 1, r = Ap >> 1;
                        if (r >= 1) mbar_wait(EA(b), (uint32_t)((r - 1) & 1));
                        loadA((la + 1) & (NC0 - 1), b);
                        cp_arrive(FA(b));
                        Ap++;
                    }
                }

                // --- consumers ---
                if (tap == 0) mbar_wait(FA(Ac & 1), (uint32_t)((Ac >> 1) & 1));
                mbar_wait(FB(Bc & 7), (uint32_t)((Bc >> 3) & 1));

                const uint32_t ab = smbase + (uint32_t)(Ac & 1) * A_BUF_B;
                const uint32_t bb = smbase + B_OFF + (uint32_t)(Bc & 7) * B_STAGE_B;
                uint32_t asl[4];
                #pragma unroll
                for (int mt = 0; mt < 4; mt++)
                    asl[mt] = aslot[tap * 256 + wm + mt * 16 + (lane & 15)];
                #pragma unroll
                for (int s16 = 0; s16 < 2; s16++) {
                    uint32_t a[4][4];
                    #pragma unroll
                    for (int mt = 0; mt < 4; mt++)
                        ldmx4(a[mt], ab + asl[mt] + (uint32_t)(s16 * 32) + a_lane);
                    uint32_t b[8][2];
                    #pragma unroll
                    for (int np = 0; np < 4; np++) {
                        uint32_t r[4];
                        ldmx4(r, bb + (uint32_t)((wn + np * 16) * A_ROW_B + s16 * 32)
                                 + b_loff);
                        b[2 * np][0] = r[0];     b[2 * np][1] = r[1];
                        b[2 * np + 1][0] = r[2]; b[2 * np + 1][1] = r[3];
                    }
                    #pragma unroll
                    for (int nt = 0; nt < 8; nt++)
                        #pragma unroll
                        for (int mt = 0; mt < 4; mt++)
                            mma16(d[mt][nt], a[mt], b[nt]);
                }

                mbar_arrive(EB(Bc & 7)); Bc++;
                if (tap == KTAPS - 1) { mbar_arrive(EA(Ac & 1)); Ac++; }
            }

            // ---- fused GroupNorm(16-ch) + ReLU epilogue for this n-block ----
            #pragma unroll
            for (int mt = 0; mt < 4; mt++) {
                #pragma unroll
                for (int h = 0; h < 2; h++) {
                    const int row = m0 + wm + mt * 16 + gid + h * 8;
                    const size_t rbase = (size_t)row * HID + n0 + wn;
                    #pragma unroll
                    for (int g = 0; g < 4; g++) {
                        const float v0 = d[mt][2 * g    ][2 * h];
                        const float v1 = d[mt][2 * g    ][2 * h + 1];
                        const float v2 = d[mt][2 * g + 1][2 * h];
                        const float v3 = d[mt][2 * g + 1][2 * h + 1];
                        float s  = v0 + v1 + v2 + v3;
                        float ss = v0 * v0 + v1 * v1 + v2 * v2 + v3 * v3;
                        s  += __shfl_xor_sync(0xffffffffu, s, 1);
                        ss += __shfl_xor_sync(0xffffffffu, ss, 1);
                        s  += __shfl_xor_sync(0xffffffffu, s, 2);
                        ss += __shfl_xor_sync(0xffffffffu, ss, 2);
                        const float mu  = s * (1.f / 16.f);
                        const float var = ss * (1.f / 16.f) - mu * mu;
                        const float rs  = rsqrtf(var + EPS);
                        const int cb = n0 + wn + 16 * g + 2 * q;
                        const float o0 = fmaxf(fmaf((v0 - mu) * rs, sgam[cb],     sbet[cb]),     0.f);
                        const float o1 = fmaxf(fmaf((v1 - mu) * rs, sgam[cb + 1], sbet[cb + 1]), 0.f);
                        const float o2 = fmaxf(fmaf((v2 - mu) * rs, sgam[cb + 8], sbet[cb + 8]), 0.f);
                        const float o3 = fmaxf(fmaf((v3 - mu) * rs, sgam[cb + 9], sbet[cb + 9]), 0.f);
                        if (LAST) {
                            *(float2*)(outF + rbase + 16 * g + 2 * q)     = make_float2(o0, o1);
                            *(float2*)(outF + rbase + 16 * g + 8 + 2 * q) = make_float2(o2, o3);
                        } else {
                            *(__half2*)(OH + rbase + 16 * g + 2 * q)     = __floats2half2_rn(o0, o1);
                            *(__half2*)(OH + rbase + 16 * g + 8 + 2 * q) = __floats2half2_rn(o2, o3);
                        }
                    }
                }
            }
        }

        __threadfence();
        __syncthreads();
        if (tid == 0) st_rel(&g_flags[u], 1);
        u = u_next;
    }
}

// ---------------------------------------------------------------------------
// Prep kernels
// ---------------------------------------------------------------------------
__global__ void reset_flags()
{
    const int i = blockIdx.x * 256 + threadIdx.x;
    g_flags[i] = 0;
    if (i == 0) g_ticket = 0u;
}
__global__ void w_prep(const float* __restrict__ W, __half* __restrict__ Wp, int CPT)
{
    __shared__ float t[32][33];
    const int bx = blockIdx.x;
    const int by = blockIdx.y;
    const int x = threadIdx.x, y = threadIdx.y;
    #pragma unroll
    for (int i = 0; i < 32; i += 8)
        t[y + i][x] = W[(size_t)(by * 32 + y + i) * 512 + bx * 32 + x];
    __syncthreads();
    const int tap = by / CPT, c0 = by - tap * CPT;
    const int cpos = c0 * KTAPS + tap;
    #pragma unroll
    for (int i = 0; i < 32; i += 8) {
        const int nl = y + i, kk = x;
        Wp[(size_t)cpos * 16384 + (size_t)(bx * 32 + nl) * 32 + kk] =
            __float2half_rn(t[kk][nl]);
    }
}
__global__ void f2h(const float* __restrict__ src, __half* __restrict__ dst)
{
    const int t = blockIdx.x * blockDim.x + threadIdx.x;
    const float4* s = (const float4*)src + 2 * (size_t)t;
    const float4 v0 = s[0], v1 = s[1];
    __half2* o = (__half2*)dst + 4 * (size_t)t;
    o[0] = __floats2half2_rn(v0.x, v0.y);
    o[1] = __floats2half2_rn(v0.z, v0.w);
    o[2] = __floats2half2_rn(v1.x, v1.y);
    o[3] = __floats2half2_rn(v1.z, v1.w);
}

// ===========================================================================
// kernel_launch: prep + flag/ticket reset + one persistent fused kernel.
// ===========================================================================
extern "C" void kernel_launch(void* const* d_in, const int* in_sizes, int n_in,
                              void* d_out, int out_size)
{
    const float* feat  = (const float*)d_in[0];
    const int*   nbr   = (const int*)  d_in[1];
    const float* w0    = (const float*)d_in[2];
    const float* wrest = (const float*)d_in[3];
    const float* gamma = (const float*)d_in[4];
    const float* beta  = (const float*)d_in[5];

    __half *actA, *actB, *featH, *Wp;
    cudaGetSymbolAddress((void**)&actA, g_actA);
    cudaGetSymbolAddress((void**)&actB, g_actB);
    cudaGetSymbolAddress((void**)&featH, g_featH);
    cudaGetSymbolAddress((void**)&Wp, g_Wp);

    cudaFuncSetAttribute(spconv_all,
                         cudaFuncAttributeMaxDynamicSharedMemorySize, SMEM_BYTES);

    f2h<<<(NSITES * 256 / 8) / 256, 256>>>(feat, featH);
    w_prep<<<dim3(16, 72), dim3(32, 8)>>>(w0, Wp, 8);
    for (int l = 0; l < 7; l++)
        w_prep<<<dim3(16, 144), dim3(32, 8)>>>(
            wrest + (size_t)l * 4608 * 512, Wp + W0H + (size_t)l * WLH, 16);
    reset_flags<<<NUNITS / 256, 256>>>();

    spconv_all<<<148, 256, SMEM_BYTES>>>(featH, nbr, Wp, gamma, beta,
                                         actA, actB, (float*)d_out);
}